// round 2
// baseline (speedup 1.0000x reference)
#include <cuda_runtime.h>
#include <math_constants.h>

#define BSZ 4
#define SEQ 2048
#define DIM 1024
#define NH  16
#define DK  64
#define ATTN_SCALE 0.125f
#define MTOT (BSZ*SEQ)   // 8192

// Scratch (device globals: allocation-guard safe)
__device__ float g_Q[MTOT*DIM];
__device__ float g_K[MTOT*DIM];
__device__ float g_V[MTOT*DIM];
__device__ float g_A[MTOT*DIM];

// ---------------------------------------------------------------------------
// SGEMM: C[8192,1024] = A[8192,1024] @ W[1024,1024] + bias
// 128x128x16 tile, 256 threads, 8x8 microtile, register double-buffered
// global loads (prefetch tile k+1 while computing tile k).
// ---------------------------------------------------------------------------
__global__ __launch_bounds__(256) void sgemm_bias(
    const float* __restrict__ A, const float* __restrict__ W,
    const float* __restrict__ bias, float* __restrict__ C)
{
    __shared__ float As[16][132];   // transposed A tile [k][m]
    __shared__ float Bs[16][132];   // W tile [k][n]

    const int tid = threadIdx.x;
    const int m0 = blockIdx.y * 128;
    const int n0 = blockIdx.x * 128;
    const int ty = tid >> 4;        // 0..15 -> rows ty*8..ty*8+7
    const int tx = tid & 15;        // 0..15 -> cols tx*8..tx*8+7

    const int arow = tid >> 2;      // 0..63
    const int ak4  = tid & 3;       // 0..3  (k quads)
    const int brow = tid >> 5;      // 0..7
    const int bcol = tid & 31;      // 0..31 (n quads)

    float acc[8][8];
    #pragma unroll
    for (int i = 0; i < 8; i++)
        #pragma unroll
        for (int j = 0; j < 8; j++) acc[i][j] = 0.f;

    const float* pA0 = &A[(m0 + arow)      * 1024 + ak4 * 4];
    const float* pA1 = &A[(m0 + arow + 64) * 1024 + ak4 * 4];
    const float* pB0 = &W[(brow)     * 1024 + n0 + bcol * 4];
    const float* pB1 = &W[(brow + 8) * 1024 + n0 + bcol * 4];

    // Preload tile 0 into registers
    float4 ra0 = *(const float4*)(pA0);
    float4 ra1 = *(const float4*)(pA1);
    float4 rb0 = *(const float4*)(pB0);
    float4 rb1 = *(const float4*)(pB1);

    for (int k0 = 0; k0 < 1024; k0 += 16) {
        // Commit prefetched registers to smem
        As[ak4*4 + 0][arow]      = ra0.x;
        As[ak4*4 + 1][arow]      = ra0.y;
        As[ak4*4 + 2][arow]      = ra0.z;
        As[ak4*4 + 3][arow]      = ra0.w;
        As[ak4*4 + 0][arow + 64] = ra1.x;
        As[ak4*4 + 1][arow + 64] = ra1.y;
        As[ak4*4 + 2][arow + 64] = ra1.z;
        As[ak4*4 + 3][arow + 64] = ra1.w;
        *(float4*)&Bs[brow][bcol * 4]     = rb0;
        *(float4*)&Bs[brow + 8][bcol * 4] = rb1;
        __syncthreads();

        // Prefetch next tile while computing this one
        if (k0 + 16 < 1024) {
            ra0 = *(const float4*)(pA0 + k0 + 16);
            ra1 = *(const float4*)(pA1 + k0 + 16);
            rb0 = *(const float4*)(pB0 + (k0 + 16) * 1024);
            rb1 = *(const float4*)(pB1 + (k0 + 16) * 1024);
        }

        #pragma unroll
        for (int k = 0; k < 16; k++) {
            float a[8], b[8];
            *(float4*)&a[0] = *(const float4*)&As[k][ty * 8];
            *(float4*)&a[4] = *(const float4*)&As[k][ty * 8 + 4];
            *(float4*)&b[0] = *(const float4*)&Bs[k][tx * 8];
            *(float4*)&b[4] = *(const float4*)&Bs[k][tx * 8 + 4];
            #pragma unroll
            for (int i = 0; i < 8; i++)
                #pragma unroll
                for (int j = 0; j < 8; j++)
                    acc[i][j] += a[i] * b[j];
        }
        __syncthreads();
    }

    float bb[8];
    #pragma unroll
    for (int j = 0; j < 8; j++) bb[j] = bias[n0 + tx * 8 + j];

    #pragma unroll
    for (int i = 0; i < 8; i++) {
        const int row = m0 + ty * 8 + i;
        #pragma unroll
        for (int j = 0; j < 8; j += 4) {
            float4 v;
            v.x = acc[i][j + 0] + bb[j + 0];
            v.y = acc[i][j + 1] + bb[j + 1];
            v.z = acc[i][j + 2] + bb[j + 2];
            v.w = acc[i][j + 3] + bb[j + 3];
            *(float4*)&C[row * 1024 + n0 + tx * 8 + j] = v;
        }
    }
}

// ---------------------------------------------------------------------------
// Flash attention, fp32. One block = (64 q-rows) x (one batch-head).
// BM=BN=64, 256 threads, 4x4 microtiles. K-tile smem buffer is XOR-swizzled
// and reused to hold P between the S phase and the O phase, so total static
// smem = 3 * 64*64 floats = 48 KB exactly.
// ---------------------------------------------------------------------------
#define SWIZ(i, j) (((i) << 6) + (((((j) >> 2) ^ ((i) & 15)) << 2) | ((j) & 3)))

__global__ __launch_bounds__(256) void attn_kernel(
    const float* __restrict__ gQ, const float* __restrict__ gK,
    const float* __restrict__ gV, const int* __restrict__ mask,
    float* __restrict__ gO)
{
    __shared__ float Qs[64 * 64];   // [d][row], swizzled, prescaled
    __shared__ float KPs[64 * 64];  // K: [d][key] swizzled; later P: [key][row] swizzled
    __shared__ float Vs[64 * 64];   // [key][d], natural

    const int tid = threadIdx.x;
    const int q0  = blockIdx.x * 64;
    const int bh  = blockIdx.y;
    const int b   = bh >> 4;
    const int h   = bh & 15;
    const int tr  = tid >> 4;       // 0..15 : rows tr*4..tr*4+3
    const int tc  = tid & 15;       // 0..15 : keys/dims tc*4..tc*4+3
    const int d4  = tid & 15;

    const int baseQ = (b * SEQ + q0) * DIM + h * DK;

    // Load Q tile, prescale by ATTN_SCALE, transpose+swizzle into smem
    #pragma unroll
    for (int p = 0; p < 4; p++) {
        const int r = (tid >> 4) + p * 16;
        float4 q = *(const float4*)&gQ[baseQ + r * DIM + d4 * 4];
        const int i0 = d4 * 4;
        Qs[SWIZ(i0 + 0, r)] = q.x * ATTN_SCALE;
        Qs[SWIZ(i0 + 1, r)] = q.y * ATTN_SCALE;
        Qs[SWIZ(i0 + 2, r)] = q.z * ATTN_SCALE;
        Qs[SWIZ(i0 + 3, r)] = q.w * ATTN_SCALE;
    }

    float m[4], l[4], o[4][4];
    #pragma unroll
    for (int r = 0; r < 4; r++) {
        m[r] = -CUDART_INF_F;
        l[r] = 0.f;
        #pragma unroll
        for (int c = 0; c < 4; c++) o[r][c] = 0.f;
    }

    const int* maskB = mask + b * SEQ;

    for (int kt = 0; kt < 32; kt++) {
        const int k0 = kt * 64;
        const int baseK = (b * SEQ + k0) * DIM + h * DK;

        // Load K (transposed+swizzled) and V (natural)
        #pragma unroll
        for (int p = 0; p < 4; p++) {
            const int r = (tid >> 4) + p * 16;
            float4 kk = *(const float4*)&gK[baseK + r * DIM + d4 * 4];
            const int i0 = d4 * 4;
            KPs[SWIZ(i0 + 0, r)] = kk.x;
            KPs[SWIZ(i0 + 1, r)] = kk.y;
            KPs[SWIZ(i0 + 2, r)] = kk.z;
            KPs[SWIZ(i0 + 3, r)] = kk.w;
            float4 vv = *(const float4*)&gV[baseK + r * DIM + d4 * 4];
            *(float4*)&Vs[r * 64 + d4 * 4] = vv;
        }
        int mk[4];
        #pragma unroll
        for (int c = 0; c < 4; c++) mk[c] = maskB[k0 + tc * 4 + c];
        __syncthreads();

        // S = (Q*scale) @ K^T  for this thread's 4x4 microtile
        float s[4][4];
        #pragma unroll
        for (int r = 0; r < 4; r++)
            #pragma unroll
            for (int c = 0; c < 4; c++) s[r][c] = 0.f;

        #pragma unroll 8
        for (int d = 0; d < 64; d++) {
            const int sx = d & 15;
            float4 a4 = *(const float4*)&Qs[(d << 6) + ((tr ^ sx) << 2)];
            float4 b4 = *(const float4*)&KPs[(d << 6) + ((tc ^ sx) << 2)];
            const float av[4] = {a4.x, a4.y, a4.z, a4.w};
            const float bv[4] = {b4.x, b4.y, b4.z, b4.w};
            #pragma unroll
            for (int r = 0; r < 4; r++)
                #pragma unroll
                for (int c = 0; c < 4; c++)
                    s[r][c] += av[r] * bv[c];
        }

        // Mask (matches reference: masked score = exactly -1e30)
        #pragma unroll
        for (int c = 0; c < 4; c++) {
            if (mk[c]) {
                #pragma unroll
                for (int r = 0; r < 4; r++) s[r][c] = -1e30f;
            }
        }

        // Online softmax update (row stats reduced over 16-lane groups)
        #pragma unroll
        for (int r = 0; r < 4; r++) {
            float tm = fmaxf(fmaxf(s[r][0], s[r][1]), fmaxf(s[r][2], s[r][3]));
            tm = fmaxf(tm, __shfl_xor_sync(0xffffffffu, tm, 1));
            tm = fmaxf(tm, __shfl_xor_sync(0xffffffffu, tm, 2));
            tm = fmaxf(tm, __shfl_xor_sync(0xffffffffu, tm, 4));
            tm = fmaxf(tm, __shfl_xor_sync(0xffffffffu, tm, 8));
            const float mn = fmaxf(m[r], tm);
            const float alpha = __expf(m[r] - mn);
            m[r] = mn;
            float rs = 0.f;
            #pragma unroll
            for (int c = 0; c < 4; c++) {
                const float pv = __expf(s[r][c] - mn);
                s[r][c] = pv;
                rs += pv;
            }
            rs += __shfl_xor_sync(0xffffffffu, rs, 1);
            rs += __shfl_xor_sync(0xffffffffu, rs, 2);
            rs += __shfl_xor_sync(0xffffffffu, rs, 4);
            rs += __shfl_xor_sync(0xffffffffu, rs, 8);
            l[r] = l[r] * alpha + rs;
            #pragma unroll
            for (int c = 0; c < 4; c++) o[r][c] *= alpha;
        }

        __syncthreads();   // everyone done reading K before P overwrites it

        // Write P into the K buffer: layout [key][row], swizzled, float4 rows
        #pragma unroll
        for (int c = 0; c < 4; c++) {
            const int key = tc * 4 + c;
            float4 pv = make_float4(s[0][c], s[1][c], s[2][c], s[3][c]);
            *(float4*)&KPs[(key << 6) + ((tr ^ (key & 15)) << 2)] = pv;
        }
        __syncthreads();

        // O += P @ V  (this thread: rows tr*4.., dims tc*4..)
        #pragma unroll 8
        for (int j = 0; j < 64; j++) {
            const int sx = j & 15;
            float4 p4 = *(const float4*)&KPs[(j << 6) + ((tr ^ sx) << 2)];
            float4 v4 = *(const float4*)&Vs[j * 64 + tc * 4];
            const float pv[4] = {p4.x, p4.y, p4.z, p4.w};
            const float vv[4] = {v4.x, v4.y, v4.z, v4.w};
            #pragma unroll
            for (int r = 0; r < 4; r++)
                #pragma unroll
                for (int c = 0; c < 4; c++)
                    o[r][c] += pv[r] * vv[c];
        }
        __syncthreads();   // before next tile's K/V load
    }

    // Normalize and store
    const int baseO = (b * SEQ + q0) * DIM + h * DK;
    #pragma unroll
    for (int r = 0; r < 4; r++) {
        const float inv = 1.f / l[r];
        float4 v = make_float4(o[r][0] * inv, o[r][1] * inv,
                               o[r][2] * inv, o[r][3] * inv);
        *(float4*)&gO[baseO + (tr * 4 + r) * DIM + tc * 4] = v;
    }
}

// ---------------------------------------------------------------------------
extern "C" void kernel_launch(void* const* d_in, const int* in_sizes, int n_in,
                              void* d_out, int out_size)
{
    const float* x    = (const float*)d_in[0];
    const int*   mask = (const int*)  d_in[1];
    const float* Wq   = (const float*)d_in[2];
    const float* bq   = (const float*)d_in[3];
    const float* Wk   = (const float*)d_in[4];
    const float* bk   = (const float*)d_in[5];
    const float* Wv   = (const float*)d_in[6];
    const float* bv   = (const float*)d_in[7];
    const float* Wf   = (const float*)d_in[8];
    const float* bf   = (const float*)d_in[9];
    float* out = (float*)d_out;

    float *Qp, *Kp, *Vp, *Ap;
    cudaGetSymbolAddress((void**)&Qp, g_Q);
    cudaGetSymbolAddress((void**)&Kp, g_K);
    cudaGetSymbolAddress((void**)&Vp, g_V);
    cudaGetSymbolAddress((void**)&Ap, g_A);

    dim3 gemm_grid(8, 64), gemm_blk(256);
    sgemm_bias<<<gemm_grid, gemm_blk>>>(x, Wq, bq, Qp);
    sgemm_bias<<<gemm_grid, gemm_blk>>>(x, Wk, bk, Kp);
    sgemm_bias<<<gemm_grid, gemm_blk>>>(x, Wv, bv, Vp);

    dim3 attn_grid(SEQ / 64, BSZ * NH), attn_blk(256);
    attn_kernel<<<attn_grid, attn_blk>>>(Qp, Kp, Vp, mask, Ap);

    sgemm_bias<<<gemm_grid, gemm_blk>>>(Ap, Wf, bf, out);
}

// round 8
// speedup vs baseline: 1.0712x; 1.0712x over previous
#include <cuda_runtime.h>
#include <math_constants.h>
#include <cstdint>

#define BSZ 4
#define SEQ 2048
#define DIM 1024
#define NH  16
#define DK  64
#define ATTN_SCALE 0.125f
#define MTOT (BSZ*SEQ)   // 8192

// Scratch (device globals: allocation-guard safe)
__device__ float g_Q[MTOT*DIM];
__device__ float g_K[MTOT*DIM];
__device__ float g_V[MTOT*DIM];
__device__ float g_A[MTOT*DIM];

// ---------------- packed f32x2 helpers (Blackwell FFMA2 path) ---------------
__device__ __forceinline__ void ffma2(uint64_t& d, uint64_t a, uint64_t b, uint64_t c) {
    asm("fma.rn.f32x2 %0, %1, %2, %3;" : "=l"(d) : "l"(a), "l"(b), "l"(c));
}
__device__ __forceinline__ void mul2(uint64_t& d, uint64_t a, uint64_t b) {
    asm("mul.rn.f32x2 %0, %1, %2;" : "=l"(d) : "l"(a), "l"(b));
}
__device__ __forceinline__ uint64_t pack2(float lo, float hi) {
    uint64_t r; asm("mov.b64 %0, {%1, %2};" : "=l"(r) : "f"(lo), "f"(hi)); return r;
}
__device__ __forceinline__ void unpack2(uint64_t v, float& lo, float& hi) {
    asm("mov.b64 {%0, %1}, %2;" : "=f"(lo), "=f"(hi) : "l"(v));
}

// ---------------------------------------------------------------------------
// SGEMM: C[8192,1024] = A[8192,1024] @ W[1024,1024] + bias
// 128x128x16 tile, 256 threads, 8x8 microtile, register double-buffered
// global loads, inner product via fma.rn.f32x2 (2 MACs/issue).
// ---------------------------------------------------------------------------
__global__ __launch_bounds__(256) void sgemm_bias(
    const float* __restrict__ A, const float* __restrict__ W,
    const float* __restrict__ bias, float* __restrict__ C)
{
    __shared__ float As[16][132];   // transposed A tile [k][m]  (row = 528B, 16B-aligned)
    __shared__ float Bs[16][132];   // W tile [k][n]

    const int tid = threadIdx.x;
    const int m0 = blockIdx.y * 128;
    const int n0 = blockIdx.x * 128;
    const int ty = tid >> 4;        // rows ty*8..+7
    const int tx = tid & 15;        // cols tx*8..+7

    const int arow = tid >> 2;      // 0..63
    const int ak4  = tid & 3;       // 0..3
    const int brow = tid >> 5;      // 0..7
    const int bcol = tid & 31;      // 0..31

    uint64_t acc2[8][4];            // [row][col-pair]
    #pragma unroll
    for (int i = 0; i < 8; i++)
        #pragma unroll
        for (int j = 0; j < 4; j++) acc2[i][j] = 0ull;

    const float* pA0 = &A[(m0 + arow)      * 1024 + ak4 * 4];
    const float* pA1 = &A[(m0 + arow + 64) * 1024 + ak4 * 4];
    const float* pB0 = &W[(brow)     * 1024 + n0 + bcol * 4];
    const float* pB1 = &W[(brow + 8) * 1024 + n0 + bcol * 4];

    float4 ra0 = *(const float4*)(pA0);
    float4 ra1 = *(const float4*)(pA1);
    float4 rb0 = *(const float4*)(pB0);
    float4 rb1 = *(const float4*)(pB1);

    for (int k0 = 0; k0 < 1024; k0 += 16) {
        As[ak4*4 + 0][arow]      = ra0.x;
        As[ak4*4 + 1][arow]      = ra0.y;
        As[ak4*4 + 2][arow]      = ra0.z;
        As[ak4*4 + 3][arow]      = ra0.w;
        As[ak4*4 + 0][arow + 64] = ra1.x;
        As[ak4*4 + 1][arow + 64] = ra1.y;
        As[ak4*4 + 2][arow + 64] = ra1.z;
        As[ak4*4 + 3][arow + 64] = ra1.w;
        *(float4*)&Bs[brow][bcol * 4]     = rb0;
        *(float4*)&Bs[brow + 8][bcol * 4] = rb1;
        __syncthreads();

        if (k0 + 16 < 1024) {
            ra0 = *(const float4*)(pA0 + k0 + 16);
            ra1 = *(const float4*)(pA1 + k0 + 16);
            rb0 = *(const float4*)(pB0 + (k0 + 16) * 1024);
            rb1 = *(const float4*)(pB1 + (k0 + 16) * 1024);
        }

        #pragma unroll
        for (int k = 0; k < 16; k++) {
            float a[8];
            *(float4*)&a[0] = *(const float4*)&As[k][ty * 8];
            *(float4*)&a[4] = *(const float4*)&As[k][ty * 8 + 4];
            // B column pairs straight from smem (adjacent floats = packed pair)
            ulonglong2 bb0 = *(const ulonglong2*)&Bs[k][tx * 8];
            ulonglong2 bb1 = *(const ulonglong2*)&Bs[k][tx * 8 + 4];
            uint64_t b2[4] = {bb0.x, bb0.y, bb1.x, bb1.y};
            #pragma unroll
            for (int i = 0; i < 8; i++) {
                const uint64_t a2 = pack2(a[i], a[i]);
                #pragma unroll
                for (int j = 0; j < 4; j++)
                    ffma2(acc2[i][j], a2, b2[j], acc2[i][j]);
            }
        }
        __syncthreads();
    }

    float bb[8];
    #pragma unroll
    for (int j = 0; j < 8; j++) bb[j] = bias[n0 + tx * 8 + j];

    #pragma unroll
    for (int i = 0; i < 8; i++) {
        const int row = m0 + ty * 8 + i;
        float c[8];
        unpack2(acc2[i][0], c[0], c[1]);
        unpack2(acc2[i][1], c[2], c[3]);
        unpack2(acc2[i][2], c[4], c[5]);
        unpack2(acc2[i][3], c[6], c[7]);
        #pragma unroll
        for (int j = 0; j < 8; j += 4) {
            float4 v;
            v.x = c[j + 0] + bb[j + 0];
            v.y = c[j + 1] + bb[j + 1];
            v.z = c[j + 2] + bb[j + 2];
            v.w = c[j + 3] + bb[j + 3];
            *(float4*)&C[row * 1024 + n0 + tx * 8 + j] = v;
        }
    }
}

// ---------------------------------------------------------------------------
// Flash attention, fp32 accumulate via fma.rn.f32x2.
// One block = (64 q-rows) x (one batch-head). BM=BN=64, 256 threads,
// 4x4 microtiles (packed as 4x2 f32x2). 48 KB static smem.
// ---------------------------------------------------------------------------
#define SWIZ(i, j) (((i) << 6) + (((((j) >> 2) ^ ((i) & 15)) << 2) | ((j) & 3)))

__global__ __launch_bounds__(256) void attn_kernel(
    const float* __restrict__ gQ, const float* __restrict__ gK,
    const float* __restrict__ gV, const int* __restrict__ mask,
    float* __restrict__ gO)
{
    __shared__ float Qs[64 * 64];   // [d][row], swizzled, prescaled
    __shared__ float KPs[64 * 64];  // K: [d][key] swizzled; later P: [key][row]
    __shared__ float Vs[64 * 64];   // [key][d], natural

    const int tid = threadIdx.x;
    const int q0  = blockIdx.x * 64;
    const int bh  = blockIdx.y;
    const int b   = bh >> 4;
    const int h   = bh & 15;
    const int tr  = tid >> 4;
    const int tc  = tid & 15;
    const int d4  = tid & 15;

    const int baseQ = (b * SEQ + q0) * DIM + h * DK;

    #pragma unroll
    for (int p = 0; p < 4; p++) {
        const int r = (tid >> 4) + p * 16;
        float4 q = *(const float4*)&gQ[baseQ + r * DIM + d4 * 4];
        const int i0 = d4 * 4;
        Qs[SWIZ(i0 + 0, r)] = q.x * ATTN_SCALE;
        Qs[SWIZ(i0 + 1, r)] = q.y * ATTN_SCALE;
        Qs[SWIZ(i0 + 2, r)] = q.z * ATTN_SCALE;
        Qs[SWIZ(i0 + 3, r)] = q.w * ATTN_SCALE;
    }

    float m[4], l[4];
    uint64_t o2[4][2];
    #pragma unroll
    for (int r = 0; r < 4; r++) {
        m[r] = -CUDART_INF_F;
        l[r] = 0.f;
        o2[r][0] = 0ull;
        o2[r][1] = 0ull;
    }

    const int* maskB = mask + b * SEQ;

    for (int kt = 0; kt < 32; kt++) {
        const int k0 = kt * 64;
        const int baseK = (b * SEQ + k0) * DIM + h * DK;

        #pragma unroll
        for (int p = 0; p < 4; p++) {
            const int r = (tid >> 4) + p * 16;
            float4 kk = *(const float4*)&gK[baseK + r * DIM + d4 * 4];
            const int i0 = d4 * 4;
            KPs[SWIZ(i0 + 0, r)] = kk.x;
            KPs[SWIZ(i0 + 1, r)] = kk.y;
            KPs[SWIZ(i0 + 2, r)] = kk.z;
            KPs[SWIZ(i0 + 3, r)] = kk.w;
            float4 vv = *(const float4*)&gV[baseK + r * DIM + d4 * 4];
            *(float4*)&Vs[r * 64 + d4 * 4] = vv;
        }
        int mk[4];
        #pragma unroll
        for (int c = 0; c < 4; c++) mk[c] = maskB[k0 + tc * 4 + c];
        __syncthreads();

        // S = (Q*scale) @ K^T, packed over key pairs
        uint64_t s2[4][2];
        #pragma unroll
        for (int r = 0; r < 4; r++) { s2[r][0] = 0ull; s2[r][1] = 0ull; }

        #pragma unroll 8
        for (int d = 0; d < 64; d++) {
            const int sx = d & 15;
            float4 a4 = *(const float4*)&Qs[(d << 6) + ((tr ^ sx) << 2)];
            ulonglong2 bb = *(const ulonglong2*)&KPs[(d << 6) + ((tc ^ sx) << 2)];
            const float av[4] = {a4.x, a4.y, a4.z, a4.w};
            #pragma unroll
            for (int r = 0; r < 4; r++) {
                const uint64_t a2 = pack2(av[r], av[r]);
                ffma2(s2[r][0], a2, bb.x, s2[r][0]);
                ffma2(s2[r][1], a2, bb.y, s2[r][1]);
            }
        }

        // Unpack to scalars for mask + softmax
        float s[4][4];
        #pragma unroll
        for (int r = 0; r < 4; r++) {
            unpack2(s2[r][0], s[r][0], s[r][1]);
            unpack2(s2[r][1], s[r][2], s[r][3]);
        }

        #pragma unroll
        for (int c = 0; c < 4; c++) {
            if (mk[c]) {
                #pragma unroll
                for (int r = 0; r < 4; r++) s[r][c] = -1e30f;
            }
        }

        #pragma unroll
        for (int r = 0; r < 4; r++) {
            float tm = fmaxf(fmaxf(s[r][0], s[r][1]), fmaxf(s[r][2], s[r][3]));
            tm = fmaxf(tm, __shfl_xor_sync(0xffffffffu, tm, 1));
            tm = fmaxf(tm, __shfl_xor_sync(0xffffffffu, tm, 2));
            tm = fmaxf(tm, __shfl_xor_sync(0xffffffffu, tm, 4));
            tm = fmaxf(tm, __shfl_xor_sync(0xffffffffu, tm, 8));
            const float mn = fmaxf(m[r], tm);
            const float alpha = __expf(m[r] - mn);
            m[r] = mn;
            float rs = 0.f;
            #pragma unroll
            for (int c = 0; c < 4; c++) {
                const float pv = __expf(s[r][c] - mn);
                s[r][c] = pv;
                rs += pv;
            }
            rs += __shfl_xor_sync(0xffffffffu, rs, 1);
            rs += __shfl_xor_sync(0xffffffffu, rs, 2);
            rs += __shfl_xor_sync(0xffffffffu, rs, 4);
            rs += __shfl_xor_sync(0xffffffffu, rs, 8);
            l[r] = l[r] * alpha + rs;
            const uint64_t al2 = pack2(alpha, alpha);
            mul2(o2[r][0], o2[r][0], al2);
            mul2(o2[r][1], o2[r][1], al2);
        }

        __syncthreads();   // everyone done reading K before P overwrites it

        // Write P into the K buffer: layout [key][row], swizzled
        #pragma unroll
        for (int c = 0; c < 4; c++) {
            const int key = tc * 4 + c;
            float4 pv = make_float4(s[0][c], s[1][c], s[2][c], s[3][c]);
            *(float4*)&KPs[(key << 6) + ((tr ^ (key & 15)) << 2)] = pv;
        }
        __syncthreads();

        // O += P @ V, packed over dim pairs
        #pragma unroll 8
        for (int j = 0; j < 64; j++) {
            const int sx = j & 15;
            float4 p4 = *(const float4*)&KPs[(j << 6) + ((tr ^ sx) << 2)];
            ulonglong2 vv = *(const ulonglong2*)&Vs[j * 64 + tc * 4];
            const float pv[4] = {p4.x, p4.y, p4.z, p4.w};
            #pragma unroll
            for (int r = 0; r < 4; r++) {
                const uint64_t p2 = pack2(pv[r], pv[r]);
                ffma2(o2[r][0], p2, vv.x, o2[r][0]);
                ffma2(o2[r][1], p2, vv.y, o2[r][1]);
            }
        }
        __syncthreads();   // before next tile's K/V load
    }

    // Normalize and store
    const int baseO = (b * SEQ + q0) * DIM + h * DK;
    #pragma unroll
    for (int r = 0; r < 4; r++) {
        const float inv = 1.f / l[r];
        float o[4];
        unpack2(o2[r][0], o[0], o[1]);
        unpack2(o2[r][1], o[2], o[3]);
        float4 v = make_float4(o[0] * inv, o[1] * inv, o[2] * inv, o[3] * inv);
        *(float4*)&gO[baseO + (tr * 4 + r) * DIM + tc * 4] = v;
    }
}

// ---------------------------------------------------------------------------
extern "C" void kernel_launch(void* const* d_in, const int* in_sizes, int n_in,
                              void* d_out, int out_size)
{
    const float* x    = (const float*)d_in[0];
    const int*   mask = (const int*)  d_in[1];
    const float* Wq   = (const float*)d_in[2];
    const float* bq   = (const float*)d_in[3];
    const float* Wk   = (const float*)d_in[4];
    const float* bk   = (const float*)d_in[5];
    const float* Wv   = (const float*)d_in[6];
    const float* bv   = (const float*)d_in[7];
    const float* Wf   = (const float*)d_in[8];
    const float* bf   = (const float*)d_in[9];
    float* out = (float*)d_out;

    float *Qp, *Kp, *Vp, *Ap;
    cudaGetSymbolAddress((void**)&Qp, g_Q);
    cudaGetSymbolAddress((void**)&Kp, g_K);
    cudaGetSymbolAddress((void**)&Vp, g_V);
    cudaGetSymbolAddress((void**)&Ap, g_A);

    dim3 gemm_grid(8, 64), gemm_blk(256);
    sgemm_bias<<<gemm_grid, gemm_blk>>>(x, Wq, bq, Qp);
    sgemm_bias<<<gemm_grid, gemm_blk>>>(x, Wk, bk, Kp);
    sgemm_bias<<<gemm_grid, gemm_blk>>>(x, Wv, bv, Vp);

    dim3 attn_grid(SEQ / 64, BSZ * NH), attn_blk(256);
    attn_kernel<<<attn_grid, attn_blk>>>(Qp, Kp, Vp, mask, Ap);

    sgemm_bias<<<gemm_grid, gemm_blk>>>(Ap, Wf, bf, out);
}

// round 10
// speedup vs baseline: 1.2847x; 1.1993x over previous
#include <cuda_runtime.h>
#include <cuda_bf16.h>
#include <math_constants.h>
#include <cstdint>

#define BSZ 4
#define SEQ 2048
#define DIM 1024
#define NH  16
#define DK  64
#define ATTN_SCALE 0.125f
#define MTOT (BSZ*SEQ)   // 8192

// ---------------- scratch (device globals: allocation-guard safe) ----------
__device__ float g_Q[MTOT*DIM];
__device__ float g_K[MTOT*DIM];
__device__ float g_V[MTOT*DIM];
__device__ float g_A[MTOT*DIM];
__device__ __nv_bfloat16 g_xh[MTOT*DIM];
__device__ __nv_bfloat16 g_xl[MTOT*DIM];
__device__ __nv_bfloat16 g_ah[MTOT*DIM];
__device__ __nv_bfloat16 g_al[MTOT*DIM];
__device__ __nv_bfloat16 g_wh[4][DIM*DIM];   // W^T hi  [n][k]
__device__ __nv_bfloat16 g_wl[4][DIM*DIM];   // W^T lo  [n][k]

// ---------------- PTX helpers ----------------------------------------------
__device__ __forceinline__ uint32_t smem_u32(const void* p) {
    uint32_t a;
    asm("{ .reg .u64 t; cvta.to.shared.u64 t, %1; cvt.u32.u64 %0, t; }"
        : "=r"(a) : "l"(p));
    return a;
}

__device__ __forceinline__ void cpasync16(uint32_t dst, const void* src) {
    asm volatile("cp.async.cg.shared.global [%0], [%1], 16;"
        :: "r"(dst), "l"(src) : "memory");
}

__device__ __forceinline__ void ldmat4(uint32_t* r, uint32_t addr) {
    asm volatile("ldmatrix.sync.aligned.m8n8.x4.shared.b16 {%0,%1,%2,%3}, [%4];"
        : "=r"(r[0]), "=r"(r[1]), "=r"(r[2]), "=r"(r[3]) : "r"(addr));
}

// D (fp32) += A (bf16) * B (bf16), m16n8k16
__device__ __forceinline__ void mma_bf16(float* d, const uint32_t* a, const uint32_t* b) {
    asm volatile("mma.sync.aligned.m16n8k16.row.col.f32.bf16.bf16.f32 "
        "{%0,%1,%2,%3}, {%4,%5,%6,%7}, {%8,%9}, {%0,%1,%2,%3};"
        : "+f"(d[0]), "+f"(d[1]), "+f"(d[2]), "+f"(d[3])
        : "r"(a[0]), "r"(a[1]), "r"(a[2]), "r"(a[3]), "r"(b[0]), "r"(b[1]));
}

// ---------------- packed f32x2 helpers (Blackwell FFMA2 path) ---------------
__device__ __forceinline__ void ffma2(uint64_t& d, uint64_t a, uint64_t b, uint64_t c) {
    asm("fma.rn.f32x2 %0, %1, %2, %3;" : "=l"(d) : "l"(a), "l"(b), "l"(c));
}
__device__ __forceinline__ void mul2(uint64_t& d, uint64_t a, uint64_t b) {
    asm("mul.rn.f32x2 %0, %1, %2;" : "=l"(d) : "l"(a), "l"(b));
}
__device__ __forceinline__ uint64_t pack2(float lo, float hi) {
    uint64_t r; asm("mov.b64 %0, {%1, %2};" : "=l"(r) : "f"(lo), "f"(hi)); return r;
}
__device__ __forceinline__ void unpack2(uint64_t v, float& lo, float& hi) {
    asm("mov.b64 {%0, %1}, %2;" : "=f"(lo), "=f"(hi) : "l"(v));
}

// ---------------------------------------------------------------------------
// Split fp32 -> bf16 hi + bf16 lo (lo = v - float(hi))
// ---------------------------------------------------------------------------
__device__ __forceinline__ uint32_t bfpack(__nv_bfloat16 a, __nv_bfloat16 b) {
    __nv_bfloat162 t = __halves2bfloat162(a, b);
    return *reinterpret_cast<uint32_t*>(&t);
}

__global__ __launch_bounds__(256) void split_f32(
    const float4* __restrict__ in, uint2* __restrict__ hi, uint2* __restrict__ lo)
{
    const int i = blockIdx.x * 256 + threadIdx.x;
    float4 v = in[i];
    __nv_bfloat16 hx = __float2bfloat16(v.x);
    __nv_bfloat16 hy = __float2bfloat16(v.y);
    __nv_bfloat16 hz = __float2bfloat16(v.z);
    __nv_bfloat16 hw = __float2bfloat16(v.w);
    __nv_bfloat16 lx = __float2bfloat16(v.x - __bfloat162float(hx));
    __nv_bfloat16 ly = __float2bfloat16(v.y - __bfloat162float(hy));
    __nv_bfloat16 lz = __float2bfloat16(v.z - __bfloat162float(hz));
    __nv_bfloat16 lw = __float2bfloat16(v.w - __bfloat162float(hw));
    hi[i] = make_uint2(bfpack(hx, hy), bfpack(hz, hw));
    lo[i] = make_uint2(bfpack(lx, ly), bfpack(lz, lw));
}

// ---------------------------------------------------------------------------
// Transpose + split W[k][n] -> Wt_hi/lo [n][k]
// ---------------------------------------------------------------------------
__global__ __launch_bounds__(256) void wsplit_t(
    const float* __restrict__ W, __nv_bfloat16* __restrict__ th,
    __nv_bfloat16* __restrict__ tl)
{
    __shared__ float s[32][33];
    const int tx = threadIdx.x, ty = threadIdx.y;
    const int bx = blockIdx.x, by = blockIdx.y;
    #pragma unroll
    for (int j = 0; j < 32; j += 8)
        s[ty + j][tx] = W[(by * 32 + ty + j) * DIM + bx * 32 + tx];
    __syncthreads();
    #pragma unroll
    for (int j = 0; j < 32; j += 8) {
        float v = s[tx][ty + j];
        __nv_bfloat16 h = __float2bfloat16(v);
        int o = (bx * 32 + ty + j) * DIM + by * 32 + tx;
        th[o] = h;
        tl[o] = __float2bfloat16(v - __bfloat162float(h));
    }
}

// ---------------------------------------------------------------------------
// HMMA split-bf16 GEMM via mma.sync (plain compute_100-compatible):
// C[8192,1024] = (Ah+Al)@(Bh+Bl)^T + bias, dropping Al*Bl.
// CTA tile 128x128, 8 warps (warp tile 32x64), BK=16, cp.async double buffer.
// Smem: 2 buffers x 4 tiles x 128 rows x 48B(padded) = 49152 B exactly.
// 48B row padding makes all ldmatrix phases bank-conflict-free
// (bank starts 12r mod 32 = {0,12,24,4,16,28,8,20}).
// ---------------------------------------------------------------------------
#define GBK   16
#define GNCH  (DIM / GBK)          // 64 chunks
#define ROWB  48                   // padded row bytes (32 data + 16 pad)
#define TILEB (128 * ROWB)         // 6144

__global__ __launch_bounds__(256) void gemm_mma_split(
    const __nv_bfloat16* __restrict__ Ah, const __nv_bfloat16* __restrict__ Al,
    const __nv_bfloat16* __restrict__ Bh, const __nv_bfloat16* __restrict__ Bl,
    const float* __restrict__ bias, float* __restrict__ C)
{
    __shared__ char smem[2][4][TILEB];   // [buf][Ah,Al,Bh,Bl][tile]

    const int tid  = threadIdx.x;
    const int lane = tid & 31, wid = tid >> 5;
    const int m0 = blockIdx.y * 128, n0 = blockIdx.x * 128;
    const int wm = (wid & 3) * 32;       // warp m offset in tile
    const int wn = (wid >> 2) * 64;      // warp n offset in tile

    // cp.async assignment: thread t -> row t/2, 16B-half t%2 (per tile)
    const int trow = tid >> 1, thalf = tid & 1;
    const char* gsrc0 = (const char*)(Ah + (size_t)(m0 + trow) * DIM) + thalf * 16;
    const char* gsrc1 = (const char*)(Al + (size_t)(m0 + trow) * DIM) + thalf * 16;
    const char* gsrc2 = (const char*)(Bh + (size_t)(n0 + trow) * DIM) + thalf * 16;
    const char* gsrc3 = (const char*)(Bl + (size_t)(n0 + trow) * DIM) + thalf * 16;
    const uint32_t doff = (uint32_t)(trow * ROWB + thalf * 16);
    const uint32_t sb0 = smem_u32(&smem[0][0][0]);
    const uint32_t sb1 = smem_u32(&smem[1][0][0]);

    // ldmatrix relative offsets (within a tile)
    // A m16k16 tile mt: matrices (m0-7,k0-7),(m8-15,k0-7),(m0-7,k8-15),(m8-15,k8-15)
    uint32_t aoff[2];
    #pragma unroll
    for (int mt = 0; mt < 2; mt++)
        aoff[mt] = (uint32_t)((wm + mt * 16 + (lane & 15)) * ROWB + (lane >> 4) * 16);
    // B pair p covers n-tiles 2p,2p+1: matrices (n0-7,k0-7),(n0-7,k8-15),(n8-15,k0-7),(n8-15,k8-15)
    uint32_t boff[4];
    #pragma unroll
    for (int p = 0; p < 4; p++)
        boff[p] = (uint32_t)((wn + p * 16 + ((lane >> 4) << 3) + (lane & 7)) * ROWB
                             + ((lane >> 3) & 1) * 16);

    float acc[2][8][4];
    #pragma unroll
    for (int mt = 0; mt < 2; mt++)
        #pragma unroll
        for (int nt = 0; nt < 8; nt++)
            #pragma unroll
            for (int i = 0; i < 4; i++) acc[mt][nt][i] = 0.f;

    auto load_chunk = [&](int c) {
        const uint32_t base = ((c & 1) ? sb1 : sb0) + doff;
        const int kb = c * 32;           // 16 bf16 = 32 bytes along K
        cpasync16(base + 0 * TILEB, gsrc0 + kb);
        cpasync16(base + 1 * TILEB, gsrc1 + kb);
        cpasync16(base + 2 * TILEB, gsrc2 + kb);
        cpasync16(base + 3 * TILEB, gsrc3 + kb);
        asm volatile("cp.async.commit_group;" ::: "memory");
    };

    load_chunk(0);

    for (int c = 0; c < GNCH; c++) {
        if (c + 1 < GNCH) {
            load_chunk(c + 1);
            asm volatile("cp.async.wait_group 1;" ::: "memory");
        } else {
            asm volatile("cp.async.wait_group 0;" ::: "memory");
        }
        __syncthreads();

        const uint32_t tb = (c & 1) ? sb1 : sb0;
        uint32_t af[2][2][4];     // [hi/lo][mt][4]
        uint32_t bf[2][8][2];     // [hi/lo][nt][2]
        #pragma unroll
        for (int h = 0; h < 2; h++) {
            const uint32_t ta = tb + h * TILEB;
            #pragma unroll
            for (int mt = 0; mt < 2; mt++) ldmat4(af[h][mt], ta + aoff[mt]);
            const uint32_t tB = tb + (2 + h) * TILEB;
            #pragma unroll
            for (int p = 0; p < 4; p++) {
                uint32_t r[4];
                ldmat4(r, tB + boff[p]);
                bf[h][p * 2 + 0][0] = r[0]; bf[h][p * 2 + 0][1] = r[1];
                bf[h][p * 2 + 1][0] = r[2]; bf[h][p * 2 + 1][1] = r[3];
            }
        }

        // three split products: Ah*Bh + Ah*Bl + Al*Bh
        #pragma unroll
        for (int mt = 0; mt < 2; mt++)
            #pragma unroll
            for (int nt = 0; nt < 8; nt++)
                mma_bf16(acc[mt][nt], af[0][mt], bf[0][nt]);
        #pragma unroll
        for (int mt = 0; mt < 2; mt++)
            #pragma unroll
            for (int nt = 0; nt < 8; nt++)
                mma_bf16(acc[mt][nt], af[0][mt], bf[1][nt]);
        #pragma unroll
        for (int mt = 0; mt < 2; mt++)
            #pragma unroll
            for (int nt = 0; nt < 8; nt++)
                mma_bf16(acc[mt][nt], af[1][mt], bf[0][nt]);

        __syncthreads();   // all warps done reading buf c&1 before it is reloaded
    }

    // Epilogue: c0,c1 -> (row, col..col+1); c2,c3 -> (row+8, ...)
    const int er = lane >> 2, ec = (lane & 3) * 2;
    #pragma unroll
    for (int mt = 0; mt < 2; mt++) {
        const int row = m0 + wm + mt * 16 + er;
        #pragma unroll
        for (int nt = 0; nt < 8; nt++) {
            const int col = n0 + wn + nt * 8 + ec;
            const float b0 = bias[col], b1 = bias[col + 1];
            float2 v0 = make_float2(acc[mt][nt][0] + b0, acc[mt][nt][1] + b1);
            float2 v1 = make_float2(acc[mt][nt][2] + b0, acc[mt][nt][3] + b1);
            *(float2*)&C[(size_t)row * DIM + col]       = v0;
            *(float2*)&C[(size_t)(row + 8) * DIM + col] = v1;
        }
    }
}

// ---------------------------------------------------------------------------
// Flash attention, fp32 FFMA2 (unchanged, known-passing R8 kernel, 2.18ms)
// ---------------------------------------------------------------------------
#define SWIZ(i, j) (((i) << 6) + (((((j) >> 2) ^ ((i) & 15)) << 2) | ((j) & 3)))

__global__ __launch_bounds__(256) void attn_kernel(
    const float* __restrict__ gQ, const float* __restrict__ gK,
    const float* __restrict__ gV, const int* __restrict__ mask,
    float* __restrict__ gO)
{
    __shared__ float Qs[64 * 64];
    __shared__ float KPs[64 * 64];
    __shared__ float Vs[64 * 64];

    const int tid = threadIdx.x;
    const int q0  = blockIdx.x * 64;
    const int bh  = blockIdx.y;
    const int b   = bh >> 4;
    const int h   = bh & 15;
    const int tr  = tid >> 4;
    const int tc  = tid & 15;
    const int d4  = tid & 15;

    const int baseQ = (b * SEQ + q0) * DIM + h * DK;

    #pragma unroll
    for (int p = 0; p < 4; p++) {
        const int r = (tid >> 4) + p * 16;
        float4 q = *(const float4*)&gQ[baseQ + r * DIM + d4 * 4];
        const int i0 = d4 * 4;
        Qs[SWIZ(i0 + 0, r)] = q.x * ATTN_SCALE;
        Qs[SWIZ(i0 + 1, r)] = q.y * ATTN_SCALE;
        Qs[SWIZ(i0 + 2, r)] = q.z * ATTN_SCALE;
        Qs[SWIZ(i0 + 3, r)] = q.w * ATTN_SCALE;
    }

    float m[4], l[4];
    uint64_t o2[4][2];
    #pragma unroll
    for (int r = 0; r < 4; r++) {
        m[r] = -CUDART_INF_F;
        l[r] = 0.f;
        o2[r][0] = 0ull;
        o2[r][1] = 0ull;
    }

    const int* maskB = mask + b * SEQ;

    for (int kt = 0; kt < 32; kt++) {
        const int k0 = kt * 64;
        const int baseK = (b * SEQ + k0) * DIM + h * DK;

        #pragma unroll
        for (int p = 0; p < 4; p++) {
            const int r = (tid >> 4) + p * 16;
            float4 kk = *(const float4*)&gK[baseK + r * DIM + d4 * 4];
            const int i0 = d4 * 4;
            KPs[SWIZ(i0 + 0, r)] = kk.x;
            KPs[SWIZ(i0 + 1, r)] = kk.y;
            KPs[SWIZ(i0 + 2, r)] = kk.z;
            KPs[SWIZ(i0 + 3, r)] = kk.w;
            float4 vv = *(const float4*)&gV[baseK + r * DIM + d4 * 4];
            *(float4*)&Vs[r * 64 + d4 * 4] = vv;
        }
        int mk[4];
        #pragma unroll
        for (int c = 0; c < 4; c++) mk[c] = maskB[k0 + tc * 4 + c];
        __syncthreads();

        uint64_t s2[4][2];
        #pragma unroll
        for (int r = 0; r < 4; r++) { s2[r][0] = 0ull; s2[r][1] = 0ull; }

        #pragma unroll 8
        for (int d = 0; d < 64; d++) {
            const int sx = d & 15;
            float4 a4 = *(const float4*)&Qs[(d << 6) + ((tr ^ sx) << 2)];
            ulonglong2 bb = *(const ulonglong2*)&KPs[(d << 6) + ((tc ^ sx) << 2)];
            const float av[4] = {a4.x, a4.y, a4.z, a4.w};
            #pragma unroll
            for (int r = 0; r < 4; r++) {
                const uint64_t a2 = pack2(av[r], av[r]);
                ffma2(s2[r][0], a2, bb.x, s2[r][0]);
                ffma2(s2[r][1], a2, bb.y, s2[r][1]);
            }
        }

        float s[4][4];
        #pragma unroll
        for (int r = 0; r < 4; r++) {
            unpack2(s2[r][0], s[r][0], s[r][1]);
            unpack2(s2[r][1], s[r][2], s[r][3]);
        }

        #pragma unroll
        for (int c = 0; c < 4; c++) {
            if (mk[c]) {
                #pragma unroll
                for (int r = 0; r < 4; r++) s[r][c] = -1e30f;
            }
        }

        #pragma unroll
        for (int r = 0; r < 4; r++) {
            float tm = fmaxf(fmaxf(s[r][0], s[r][1]), fmaxf(s[r][2], s[r][3]));
            tm = fmaxf(tm, __shfl_xor_sync(0xffffffffu, tm, 1));
            tm = fmaxf(tm, __shfl_xor_sync(0xffffffffu, tm, 2));
            tm = fmaxf(tm, __shfl_xor_sync(0xffffffffu, tm, 4));
            tm = fmaxf(tm, __shfl_xor_sync(0xffffffffu, tm, 8));
            const float mn = fmaxf(m[r], tm);
            const float alpha = __expf(m[r] - mn);
            m[r] = mn;
            float rs = 0.f;
            #pragma unroll
            for (int c = 0; c < 4; c++) {
                const float pv = __expf(s[r][c] - mn);
                s[r][c] = pv;
                rs += pv;
            }
            rs += __shfl_xor_sync(0xffffffffu, rs, 1);
            rs += __shfl_xor_sync(0xffffffffu, rs, 2);
            rs += __shfl_xor_sync(0xffffffffu, rs, 4);
            rs += __shfl_xor_sync(0xffffffffu, rs, 8);
            l[r] = l[r] * alpha + rs;
            const uint64_t al2 = pack2(alpha, alpha);
            mul2(o2[r][0], o2[r][0], al2);
            mul2(o2[r][1], o2[r][1], al2);
        }

        __syncthreads();

        #pragma unroll
        for (int c = 0; c < 4; c++) {
            const int key = tc * 4 + c;
            float4 pv = make_float4(s[0][c], s[1][c], s[2][c], s[3][c]);
            *(float4*)&KPs[(key << 6) + ((tr ^ (key & 15)) << 2)] = pv;
        }
        __syncthreads();

        #pragma unroll 8
        for (int j = 0; j < 64; j++) {
            const int sx = j & 15;
            float4 p4 = *(const float4*)&KPs[(j << 6) + ((tr ^ sx) << 2)];
            ulonglong2 vv = *(const ulonglong2*)&Vs[j * 64 + tc * 4];
            const float pv[4] = {p4.x, p4.y, p4.z, p4.w};
            #pragma unroll
            for (int r = 0; r < 4; r++) {
                const uint64_t p2 = pack2(pv[r], pv[r]);
                ffma2(o2[r][0], p2, vv.x, o2[r][0]);
                ffma2(o2[r][1], p2, vv.y, o2[r][1]);
            }
        }
        __syncthreads();
    }

    const int baseO = (b * SEQ + q0) * DIM + h * DK;
    #pragma unroll
    for (int r = 0; r < 4; r++) {
        const float inv = 1.f / l[r];
        float o[4];
        unpack2(o2[r][0], o[0], o[1]);
        unpack2(o2[r][1], o[2], o[3]);
        float4 v = make_float4(o[0] * inv, o[1] * inv, o[2] * inv, o[3] * inv);
        *(float4*)&gO[baseO + (tr * 4 + r) * DIM + tc * 4] = v;
    }
}

// ---------------------------------------------------------------------------
extern "C" void kernel_launch(void* const* d_in, const int* in_sizes, int n_in,
                              void* d_out, int out_size)
{
    const float* x    = (const float*)d_in[0];
    const int*   mask = (const int*)  d_in[1];
    const float* Wq   = (const float*)d_in[2];
    const float* bq   = (const float*)d_in[3];
    const float* Wk   = (const float*)d_in[4];
    const float* bk   = (const float*)d_in[5];
    const float* Wv   = (const float*)d_in[6];
    const float* bv   = (const float*)d_in[7];
    const float* Wf   = (const float*)d_in[8];
    const float* bf   = (const float*)d_in[9];
    float* out = (float*)d_out;

    float *Qp, *Kp, *Vp, *Ap;
    cudaGetSymbolAddress((void**)&Qp, g_Q);
    cudaGetSymbolAddress((void**)&Kp, g_K);
    cudaGetSymbolAddress((void**)&Vp, g_V);
    cudaGetSymbolAddress((void**)&Ap, g_A);
    __nv_bfloat16 *xh, *xl, *ah, *al, *wh, *wl;
    cudaGetSymbolAddress((void**)&xh, g_xh);
    cudaGetSymbolAddress((void**)&xl, g_xl);
    cudaGetSymbolAddress((void**)&ah, g_ah);
    cudaGetSymbolAddress((void**)&al, g_al);
    cudaGetSymbolAddress((void**)&wh, g_wh);
    cudaGetSymbolAddress((void**)&wl, g_wl);

    const int n4 = MTOT * DIM / 4;         // 2M float4s
    dim3 tblk(32, 8), tgrd(32, 32);
    dim3 ggrd(8, 64), gblk(256);

    split_f32<<<n4 / 256, 256>>>((const float4*)x, (uint2*)xh, (uint2*)xl);
    wsplit_t<<<tgrd, tblk>>>(Wq, wh + 0 * DIM * DIM, wl + 0 * DIM * DIM);
    wsplit_t<<<tgrd, tblk>>>(Wk, wh + 1 * DIM * DIM, wl + 1 * DIM * DIM);
    wsplit_t<<<tgrd, tblk>>>(Wv, wh + 2 * DIM * DIM, wl + 2 * DIM * DIM);
    wsplit_t<<<tgrd, tblk>>>(Wf, wh + 3 * DIM * DIM, wl + 3 * DIM * DIM);

    gemm_mma_split<<<ggrd, gblk>>>(xh, xl, wh + 0 * DIM * DIM,
                                   wl + 0 * DIM * DIM, bq, Qp);
    gemm_mma_split<<<ggrd, gblk>>>(xh, xl, wh + 1 * DIM * DIM,
                                   wl + 1 * DIM * DIM, bk, Kp);
    gemm_mma_split<<<ggrd, gblk>>>(xh, xl, wh + 2 * DIM * DIM,
                                   wl + 2 * DIM * DIM, bv, Vp);

    dim3 attn_grid(SEQ / 64, BSZ * NH), attn_blk(256);
    attn_kernel<<<attn_grid, attn_blk>>>(Qp, Kp, Vp, mask, Ap);

    split_f32<<<n4 / 256, 256>>>((const float4*)Ap, (uint2*)ah, (uint2*)al);
    gemm_mma_split<<<ggrd, gblk>>>(ah, al, wh + 3 * DIM * DIM,
                                   wl + 3 * DIM * DIM, bf, out);
}

// round 13
// speedup vs baseline: 2.3716x; 1.8460x over previous
#include <cuda_runtime.h>
#include <cuda_bf16.h>
#include <math_constants.h>
#include <cstdint>

#define BSZ 4
#define SEQ 2048
#define DIM 1024
#define NH  16
#define DK  64
#define ATTN_SCALE 0.125f
#define MTOT (BSZ*SEQ)   // 8192

// ---------------- scratch (device globals: allocation-guard safe) ----------
__device__ float g_Q[MTOT*DIM];
__device__ float g_K[MTOT*DIM];
__device__ float g_V[MTOT*DIM];
__device__ float g_A[MTOT*DIM];
__device__ __nv_bfloat16 g_xh[MTOT*DIM];
__device__ __nv_bfloat16 g_xl[MTOT*DIM];
__device__ __nv_bfloat16 g_ah[MTOT*DIM];
__device__ __nv_bfloat16 g_al[MTOT*DIM];
__device__ __nv_bfloat16 g_qh[MTOT*DIM];
__device__ __nv_bfloat16 g_ql[MTOT*DIM];
__device__ __nv_bfloat16 g_kh[MTOT*DIM];
__device__ __nv_bfloat16 g_kl[MTOT*DIM];
__device__ __nv_bfloat16 g_vh[MTOT*DIM];
__device__ __nv_bfloat16 g_vl[MTOT*DIM];
__device__ __nv_bfloat16 g_wh[4][DIM*DIM];   // W^T hi  [n][k]
__device__ __nv_bfloat16 g_wl[4][DIM*DIM];   // W^T lo  [n][k]

// ---------------- PTX helpers ----------------------------------------------
__device__ __forceinline__ uint32_t smem_u32(const void* p) {
    uint32_t a;
    asm("{ .reg .u64 t; cvta.to.shared.u64 t, %1; cvt.u32.u64 %0, t; }"
        : "=r"(a) : "l"(p));
    return a;
}

__device__ __forceinline__ void cpasync16(uint32_t dst, const void* src) {
    asm volatile("cp.async.cg.shared.global [%0], [%1], 16;"
        :: "r"(dst), "l"(src) : "memory");
}

__device__ __forceinline__ void ldmat4(uint32_t* r, uint32_t addr) {
    asm volatile("ldmatrix.sync.aligned.m8n8.x4.shared.b16 {%0,%1,%2,%3}, [%4];"
        : "=r"(r[0]), "=r"(r[1]), "=r"(r[2]), "=r"(r[3]) : "r"(addr));
}

__device__ __forceinline__ void ldmat4t(uint32_t* r, uint32_t addr) {
    asm volatile("ldmatrix.sync.aligned.m8n8.x4.trans.shared.b16 {%0,%1,%2,%3}, [%4];"
        : "=r"(r[0]), "=r"(r[1]), "=r"(r[2]), "=r"(r[3]) : "r"(addr));
}

// D (fp32) += A (bf16) * B (bf16), m16n8k16
__device__ __forceinline__ void mma_bf16(float* d, const uint32_t* a, const uint32_t* b) {
    asm volatile("mma.sync.aligned.m16n8k16.row.col.f32.bf16.bf16.f32 "
        "{%0,%1,%2,%3}, {%4,%5,%6,%7}, {%8,%9}, {%0,%1,%2,%3};"
        : "+f"(d[0]), "+f"(d[1]), "+f"(d[2]), "+f"(d[3])
        : "r"(a[0]), "r"(a[1]), "r"(a[2]), "r"(a[3]), "r"(b[0]), "r"(b[1]));
}

// pack two f32 -> bf16x2 register {hi, lo}
__device__ __forceinline__ uint32_t cvt2(float hi, float lo) {
    uint32_t r;
    asm("cvt.rn.bf16x2.f32 %0, %1, %2;" : "=r"(r) : "f"(hi), "f"(lo));
    return r;
}

// ---------------------------------------------------------------------------
// Split fp32*scale -> bf16 hi + bf16 lo
// ---------------------------------------------------------------------------
__device__ __forceinline__ uint32_t bfpack(__nv_bfloat16 a, __nv_bfloat16 b) {
    __nv_bfloat162 t = __halves2bfloat162(a, b);
    return *reinterpret_cast<uint32_t*>(&t);
}

__global__ __launch_bounds__(256) void split_f32(
    const float4* __restrict__ in, uint2* __restrict__ hi, uint2* __restrict__ lo,
    float scale)
{
    const int i = blockIdx.x * 256 + threadIdx.x;
    float4 v = in[i];
    v.x *= scale; v.y *= scale; v.z *= scale; v.w *= scale;
    __nv_bfloat16 hx = __float2bfloat16(v.x);
    __nv_bfloat16 hy = __float2bfloat16(v.y);
    __nv_bfloat16 hz = __float2bfloat16(v.z);
    __nv_bfloat16 hw = __float2bfloat16(v.w);
    __nv_bfloat16 lx = __float2bfloat16(v.x - __bfloat162float(hx));
    __nv_bfloat16 ly = __float2bfloat16(v.y - __bfloat162float(hy));
    __nv_bfloat16 lz = __float2bfloat16(v.z - __bfloat162float(hz));
    __nv_bfloat16 lw = __float2bfloat16(v.w - __bfloat162float(hw));
    hi[i] = make_uint2(bfpack(hx, hy), bfpack(hz, hw));
    lo[i] = make_uint2(bfpack(lx, ly), bfpack(lz, lw));
}

// ---------------------------------------------------------------------------
// Transpose + split W[k][n] -> Wt_hi/lo [n][k]
// ---------------------------------------------------------------------------
__global__ __launch_bounds__(256) void wsplit_t(
    const float* __restrict__ W, __nv_bfloat16* __restrict__ th,
    __nv_bfloat16* __restrict__ tl)
{
    __shared__ float s[32][33];
    const int tx = threadIdx.x, ty = threadIdx.y;
    const int bx = blockIdx.x, by = blockIdx.y;
    #pragma unroll
    for (int j = 0; j < 32; j += 8)
        s[ty + j][tx] = W[(by * 32 + ty + j) * DIM + bx * 32 + tx];
    __syncthreads();
    #pragma unroll
    for (int j = 0; j < 32; j += 8) {
        float v = s[tx][ty + j];
        __nv_bfloat16 h = __float2bfloat16(v);
        int o = (bx * 32 + ty + j) * DIM + by * 32 + tx;
        th[o] = h;
        tl[o] = __float2bfloat16(v - __bfloat162float(h));
    }
}

// ---------------------------------------------------------------------------
// HMMA split-bf16 GEMM (unchanged from R10, passing)
// ---------------------------------------------------------------------------
#define GBK   16
#define GNCH  (DIM / GBK)          // 64 chunks
#define ROWB  48
#define TILEB (128 * ROWB)

__global__ __launch_bounds__(256) void gemm_mma_split(
    const __nv_bfloat16* __restrict__ Ah, const __nv_bfloat16* __restrict__ Al,
    const __nv_bfloat16* __restrict__ Bh, const __nv_bfloat16* __restrict__ Bl,
    const float* __restrict__ bias, float* __restrict__ C)
{
    __shared__ char smem[2][4][TILEB];

    const int tid  = threadIdx.x;
    const int lane = tid & 31, wid = tid >> 5;
    const int m0 = blockIdx.y * 128, n0 = blockIdx.x * 128;
    const int wm = (wid & 3) * 32;
    const int wn = (wid >> 2) * 64;

    const int trow = tid >> 1, thalf = tid & 1;
    const char* gsrc0 = (const char*)(Ah + (size_t)(m0 + trow) * DIM) + thalf * 16;
    const char* gsrc1 = (const char*)(Al + (size_t)(m0 + trow) * DIM) + thalf * 16;
    const char* gsrc2 = (const char*)(Bh + (size_t)(n0 + trow) * DIM) + thalf * 16;
    const char* gsrc3 = (const char*)(Bl + (size_t)(n0 + trow) * DIM) + thalf * 16;
    const uint32_t doff = (uint32_t)(trow * ROWB + thalf * 16);
    const uint32_t sb0 = smem_u32(&smem[0][0][0]);
    const uint32_t sb1 = smem_u32(&smem[1][0][0]);

    uint32_t aoff[2];
    #pragma unroll
    for (int mt = 0; mt < 2; mt++)
        aoff[mt] = (uint32_t)((wm + mt * 16 + (lane & 15)) * ROWB + (lane >> 4) * 16);
    uint32_t boff[4];
    #pragma unroll
    for (int p = 0; p < 4; p++)
        boff[p] = (uint32_t)((wn + p * 16 + ((lane >> 4) << 3) + (lane & 7)) * ROWB
                             + ((lane >> 3) & 1) * 16);

    float acc[2][8][4];
    #pragma unroll
    for (int mt = 0; mt < 2; mt++)
        #pragma unroll
        for (int nt = 0; nt < 8; nt++)
            #pragma unroll
            for (int i = 0; i < 4; i++) acc[mt][nt][i] = 0.f;

    auto load_chunk = [&](int c) {
        const uint32_t base = ((c & 1) ? sb1 : sb0) + doff;
        const int kb = c * 32;
        cpasync16(base + 0 * TILEB, gsrc0 + kb);
        cpasync16(base + 1 * TILEB, gsrc1 + kb);
        cpasync16(base + 2 * TILEB, gsrc2 + kb);
        cpasync16(base + 3 * TILEB, gsrc3 + kb);
        asm volatile("cp.async.commit_group;" ::: "memory");
    };

    load_chunk(0);

    for (int c = 0; c < GNCH; c++) {
        if (c + 1 < GNCH) {
            load_chunk(c + 1);
            asm volatile("cp.async.wait_group 1;" ::: "memory");
        } else {
            asm volatile("cp.async.wait_group 0;" ::: "memory");
        }
        __syncthreads();

        const uint32_t tb = (c & 1) ? sb1 : sb0;
        uint32_t af[2][2][4];
        uint32_t bf[2][8][2];
        #pragma unroll
        for (int h = 0; h < 2; h++) {
            const uint32_t ta = tb + h * TILEB;
            #pragma unroll
            for (int mt = 0; mt < 2; mt++) ldmat4(af[h][mt], ta + aoff[mt]);
            const uint32_t tB = tb + (2 + h) * TILEB;
            #pragma unroll
            for (int p = 0; p < 4; p++) {
                uint32_t r[4];
                ldmat4(r, tB + boff[p]);
                bf[h][p * 2 + 0][0] = r[0]; bf[h][p * 2 + 0][1] = r[1];
                bf[h][p * 2 + 1][0] = r[2]; bf[h][p * 2 + 1][1] = r[3];
            }
        }

        #pragma unroll
        for (int mt = 0; mt < 2; mt++)
            #pragma unroll
            for (int nt = 0; nt < 8; nt++)
                mma_bf16(acc[mt][nt], af[0][mt], bf[0][nt]);
        #pragma unroll
        for (int mt = 0; mt < 2; mt++)
            #pragma unroll
            for (int nt = 0; nt < 8; nt++)
                mma_bf16(acc[mt][nt], af[0][mt], bf[1][nt]);
        #pragma unroll
        for (int mt = 0; mt < 2; mt++)
            #pragma unroll
            for (int nt = 0; nt < 8; nt++)
                mma_bf16(acc[mt][nt], af[1][mt], bf[0][nt]);

        __syncthreads();
    }

    const int er = lane >> 2, ec = (lane & 3) * 2;
    #pragma unroll
    for (int mt = 0; mt < 2; mt++) {
        const int row = m0 + wm + mt * 16 + er;
        #pragma unroll
        for (int nt = 0; nt < 8; nt++) {
            const int col = n0 + wn + nt * 8 + ec;
            const float b0 = bias[col], b1 = bias[col + 1];
            float2 v0 = make_float2(acc[mt][nt][0] + b0, acc[mt][nt][1] + b1);
            float2 v1 = make_float2(acc[mt][nt][2] + b0, acc[mt][nt][3] + b1);
            *(float2*)&C[(size_t)row * DIM + col]       = v0;
            *(float2*)&C[(size_t)(row + 8) * DIM + col] = v1;
        }
    }
}

// ---------------------------------------------------------------------------
// Flash attention via mma.sync bf16 hi/lo split.
// CTA = 128 q-rows x 1 (b,h). 8 warps x 16 rows. 64-key tiles, 32 tiles.
// Smem: 3-slot ring x 16 KB = 48 KB static. Slot = [Hhalf 8KB | Lhalf 8KB],
// each half 64 rows x 128 B with 16B-unit XOR swizzle (u ^= row&7).
// Q fragments in registers; P reuses S accumulator fragments (FA2 mapping).
// ---------------------------------------------------------------------------
#define ANKT (SEQ / 64)            // 32 key tiles

__global__ __launch_bounds__(256) void attn_mma(
    const __nv_bfloat16* __restrict__ qh, const __nv_bfloat16* __restrict__ ql,
    const __nv_bfloat16* __restrict__ kh, const __nv_bfloat16* __restrict__ kl,
    const __nv_bfloat16* __restrict__ vh, const __nv_bfloat16* __restrict__ vl,
    const int* __restrict__ mask, float* __restrict__ gO)
{
    __shared__ char ring[3][16384];

    const int tid = threadIdx.x, lane = tid & 31, w = tid >> 5;
    const int q0 = blockIdx.x * 128;
    const int bh_ = blockIdx.y;
    const int b = bh_ >> 4, h = bh_ & 15;
    const int er = lane >> 2, qq = lane & 3;

    uint32_t rb[3];
    rb[0] = smem_u32(ring[0]); rb[1] = smem_u32(ring[1]); rb[2] = smem_u32(ring[2]);

    // ---- stage Q (Qh -> slot0, Ql -> slot1), swizzled -----------------------
    {
        const int row = tid >> 1;
        const int u0 = (tid & 1) * 4;
        const char* sh = (const char*)(qh + (size_t)(b * SEQ + q0 + row) * DIM + h * DK);
        const char* sl = (const char*)(ql + (size_t)(b * SEQ + q0 + row) * DIM + h * DK);
        #pragma unroll
        for (int u = 0; u < 4; u++) {
            const uint32_t off = (uint32_t)(row * 128 + (((u0 + u) ^ (row & 7)) << 4));
            cpasync16(rb[0] + off, sh + (u0 + u) * 16);
            cpasync16(rb[1] + off, sl + (u0 + u) * 16);
        }
        asm volatile("cp.async.commit_group;" ::: "memory");
        asm volatile("cp.async.wait_group 0;" ::: "memory");
        __syncthreads();
    }

    // Q fragments: [h/l][kstep][4]
    uint32_t qf[2][4][4];
    {
        const int row = w * 16 + (lane & 15);
        const int rx = row & 7;
        #pragma unroll
        for (int ks = 0; ks < 4; ks++) {
            const uint32_t addr = (uint32_t)(row * 128 + (((2 * ks + (lane >> 4)) ^ rx) << 4));
            ldmat4(qf[0][ks], rb[0] + addr);
            ldmat4(qf[1][ks], rb[1] + addr);
        }
    }
    __syncthreads();   // ring slots free for K/V now

    // lane-constant address parts
    const int kx = lane & 7;
    const uint32_t kkbase = (uint32_t)(((((lane >> 4) << 3) + (lane & 7))) * 128);
    const uint32_t kvbase = (uint32_t)(((((lane >> 3) & 1) << 3) + (lane & 7)) * 128);
    uint32_t xk[4], xv[4];
    #pragma unroll
    for (int ks = 0; ks < 4; ks++)
        xk[ks] = (uint32_t)((((2 * ks + ((lane >> 3) & 1)) ^ kx)) << 4);
    #pragma unroll
    for (int t = 0; t < 4; t++)
        xv[t] = (uint32_t)((((2 * t + (lane >> 4)) ^ kx)) << 4);

    // resource loader: r even -> K tile r/2, r odd -> V tile r/2; slot r%3
    const int lrow = tid >> 2;
    const int lu0 = (tid & 3) * 2;
    auto load_res = [&](int r) {
        const int kt = r >> 1;
        const __nv_bfloat16* sh = (r & 1) ? vh : kh;
        const __nv_bfloat16* sl = (r & 1) ? vl : kl;
        const char* gh = (const char*)(sh + (size_t)(b * SEQ + kt * 64 + lrow) * DIM + h * DK);
        const char* gl = (const char*)(sl + (size_t)(b * SEQ + kt * 64 + lrow) * DIM + h * DK);
        const uint32_t base = rb[r % 3] + (uint32_t)(lrow * 128);
        #pragma unroll
        for (int u = 0; u < 2; u++) {
            const uint32_t off = (uint32_t)((((lu0 + u) ^ (lrow & 7)) << 4));
            cpasync16(base + off,        gh + (lu0 + u) * 16);
            cpasync16(base + 8192 + off, gl + (lu0 + u) * 16);
        }
        asm volatile("cp.async.commit_group;" ::: "memory");
    };

    float m[2] = {-CUDART_INF_F, -CUDART_INF_F};
    float l[2] = {0.f, 0.f};
    float oacc[8][4];
    #pragma unroll
    for (int n = 0; n < 8; n++)
        #pragma unroll
        for (int i = 0; i < 4; i++) oacc[n][i] = 0.f;

    uint32_t phx[8], phy[8], plx[8], ply[8];
    const int* maskB = mask + b * SEQ;

    load_res(0);
    load_res(1);

    #pragma unroll 1
    for (int kt = 0; kt < ANKT; kt++) {
        // ================= S step (resource 2kt, slot (2kt)%3) ==============
        if (kt + 1 < ANKT) {
            load_res(2 * kt + 2);
            asm volatile("cp.async.wait_group 2;" ::: "memory");
        } else {
            asm volatile("cp.async.wait_group 1;" ::: "memory");
        }
        __syncthreads();
        {
            const uint32_t sb = rb[(2 * kt) % 3];
            float sacc[8][4];
            #pragma unroll
            for (int n = 0; n < 8; n++)
                #pragma unroll
                for (int i = 0; i < 4; i++) sacc[n][i] = 0.f;

            #pragma unroll
            for (int ks = 0; ks < 4; ks++) {
                uint32_t bf_[4][4];
                #pragma unroll
                for (int p = 0; p < 4; p++)
                    ldmat4(bf_[p], sb + p * 2048 + kkbase + xk[ks]);
                #pragma unroll
                for (int nt = 0; nt < 8; nt++)
                    mma_bf16(sacc[nt], qf[0][ks], &bf_[nt >> 1][(nt & 1) * 2]);
                #pragma unroll
                for (int nt = 0; nt < 8; nt++)
                    mma_bf16(sacc[nt], qf[1][ks], &bf_[nt >> 1][(nt & 1) * 2]);
                #pragma unroll
                for (int p = 0; p < 4; p++)
                    ldmat4(bf_[p], sb + 8192 + p * 2048 + kkbase + xk[ks]);
                #pragma unroll
                for (int nt = 0; nt < 8; nt++)
                    mma_bf16(sacc[nt], qf[0][ks], &bf_[nt >> 1][(nt & 1) * 2]);
            }

            // mask (exactly -1e30, as reference), row max
            float mx0 = -CUDART_INF_F, mx1 = -CUDART_INF_F;
            #pragma unroll
            for (int nt = 0; nt < 8; nt++) {
                int2 mk = *(const int2*)&maskB[kt * 64 + nt * 8 + 2 * qq];
                if (mk.x) { sacc[nt][0] = -1e30f; sacc[nt][2] = -1e30f; }
                if (mk.y) { sacc[nt][1] = -1e30f; sacc[nt][3] = -1e30f; }
                mx0 = fmaxf(mx0, fmaxf(sacc[nt][0], sacc[nt][1]));
                mx1 = fmaxf(mx1, fmaxf(sacc[nt][2], sacc[nt][3]));
            }
            mx0 = fmaxf(mx0, __shfl_xor_sync(0xffffffffu, mx0, 1));
            mx0 = fmaxf(mx0, __shfl_xor_sync(0xffffffffu, mx0, 2));
            mx1 = fmaxf(mx1, __shfl_xor_sync(0xffffffffu, mx1, 1));
            mx1 = fmaxf(mx1, __shfl_xor_sync(0xffffffffu, mx1, 2));

            const float mn0 = fmaxf(m[0], mx0), mn1 = fmaxf(m[1], mx1);
            const float al0 = __expf(m[0] - mn0), al1 = __expf(m[1] - mn1);
            m[0] = mn0; m[1] = mn1;

            float rs0 = 0.f, rs1 = 0.f;
            #pragma unroll
            for (int nt = 0; nt < 8; nt++) {
                const float p0 = __expf(sacc[nt][0] - mn0);
                const float p1 = __expf(sacc[nt][1] - mn0);
                const float p2 = __expf(sacc[nt][2] - mn1);
                const float p3 = __expf(sacc[nt][3] - mn1);
                rs0 += p0 + p1; rs1 += p2 + p3;
                const uint32_t hA = cvt2(p1, p0);
                const uint32_t hB = cvt2(p3, p2);
                phx[nt] = hA; phy[nt] = hB;
                plx[nt] = cvt2(p1 - __uint_as_float(hA & 0xffff0000u),
                               p0 - __uint_as_float(hA << 16));
                ply[nt] = cvt2(p3 - __uint_as_float(hB & 0xffff0000u),
                               p2 - __uint_as_float(hB << 16));
            }
            rs0 += __shfl_xor_sync(0xffffffffu, rs0, 1);
            rs0 += __shfl_xor_sync(0xffffffffu, rs0, 2);
            rs1 += __shfl_xor_sync(0xffffffffu, rs1, 1);
            rs1 += __shfl_xor_sync(0xffffffffu, rs1, 2);
            l[0] = l[0] * al0 + rs0;
            l[1] = l[1] * al1 + rs1;

            #pragma unroll
            for (int n = 0; n < 8; n++) {
                oacc[n][0] *= al0; oacc[n][1] *= al0;
                oacc[n][2] *= al1; oacc[n][3] *= al1;
            }
        }
        __syncthreads();

        // ================= PV step (resource 2kt+1, slot (2kt+1)%3) =========
        if (kt + 1 < ANKT) {
            load_res(2 * kt + 3);
            asm volatile("cp.async.wait_group 2;" ::: "memory");
        } else {
            asm volatile("cp.async.wait_group 0;" ::: "memory");
        }
        __syncthreads();
        {
            const uint32_t sb = rb[(2 * kt + 1) % 3];
            #pragma unroll
            for (int j = 0; j < 4; j++) {
                uint32_t aH[4] = {phx[2 * j], phy[2 * j], phx[2 * j + 1], phy[2 * j + 1]};
                uint32_t aL[4] = {plx[2 * j], ply[2 * j], plx[2 * j + 1], ply[2 * j + 1]};
                uint32_t bv_[4][4];
                #pragma unroll
                for (int t = 0; t < 4; t++)
                    ldmat4t(bv_[t], sb + j * 2048 + kvbase + xv[t]);
                #pragma unroll
                for (int n = 0; n < 8; n++)
                    mma_bf16(oacc[n], aH, &bv_[n >> 1][(n & 1) * 2]);
                #pragma unroll
                for (int n = 0; n < 8; n++)
                    mma_bf16(oacc[n], aL, &bv_[n >> 1][(n & 1) * 2]);
                #pragma unroll
                for (int t = 0; t < 4; t++)
                    ldmat4t(bv_[t], sb + 8192 + j * 2048 + kvbase + xv[t]);
                #pragma unroll
                for (int n = 0; n < 8; n++)
                    mma_bf16(oacc[n], aH, &bv_[n >> 1][(n & 1) * 2]);
            }
        }
        __syncthreads();
    }

    // ---- epilogue ----------------------------------------------------------
    const float inv0 = 1.f / l[0], inv1 = 1.f / l[1];
    const int row0 = b * SEQ + q0 + w * 16 + er;
    float* o0 = gO + (size_t)row0 * DIM + h * DK + 2 * qq;
    float* o1 = o0 + (size_t)8 * DIM;
    #pragma unroll
    for (int n = 0; n < 8; n++) {
        *(float2*)(o0 + n * 8) = make_float2(oacc[n][0] * inv0, oacc[n][1] * inv0);
        *(float2*)(o1 + n * 8) = make_float2(oacc[n][2] * inv1, oacc[n][3] * inv1);
    }
}

// ---------------------------------------------------------------------------
extern "C" void kernel_launch(void* const* d_in, const int* in_sizes, int n_in,
                              void* d_out, int out_size)
{
    const float* x    = (const float*)d_in[0];
    const int*   mask = (const int*)  d_in[1];
    const float* Wq   = (const float*)d_in[2];
    const float* bq   = (const float*)d_in[3];
    const float* Wk   = (const float*)d_in[4];
    const float* bk   = (const float*)d_in[5];
    const float* Wv   = (const float*)d_in[6];
    const float* bv   = (const float*)d_in[7];
    const float* Wf   = (const float*)d_in[8];
    const float* bf   = (const float*)d_in[9];
    float* out = (float*)d_out;

    float *Qp, *Kp, *Vp, *Ap;
    cudaGetSymbolAddress((void**)&Qp, g_Q);
    cudaGetSymbolAddress((void**)&Kp, g_K);
    cudaGetSymbolAddress((void**)&Vp, g_V);
    cudaGetSymbolAddress((void**)&Ap, g_A);
    __nv_bfloat16 *xh, *xl, *ah, *al, *wh, *wl, *qh, *ql, *kh, *kl, *vh, *vl;
    cudaGetSymbolAddress((void**)&xh, g_xh);
    cudaGetSymbolAddress((void**)&xl, g_xl);
    cudaGetSymbolAddress((void**)&ah, g_ah);
    cudaGetSymbolAddress((void**)&al, g_al);
    cudaGetSymbolAddress((void**)&wh, g_wh);
    cudaGetSymbolAddress((void**)&wl, g_wl);
    cudaGetSymbolAddress((void**)&qh, g_qh);
    cudaGetSymbolAddress((void**)&ql, g_ql);
    cudaGetSymbolAddress((void**)&kh, g_kh);
    cudaGetSymbolAddress((void**)&kl, g_kl);
    cudaGetSymbolAddress((void**)&vh, g_vh);
    cudaGetSymbolAddress((void**)&vl, g_vl);

    const int n4 = MTOT * DIM / 4;
    dim3 tblk(32, 8), tgrd(32, 32);
    dim3 ggrd(8, 64), gblk(256);

    split_f32<<<n4 / 256, 256>>>((const float4*)x, (uint2*)xh, (uint2*)xl, 1.f);
    wsplit_t<<<tgrd, tblk>>>(Wq, wh + 0 * DIM * DIM, wl + 0 * DIM * DIM);
    wsplit_t<<<tgrd, tblk>>>(Wk, wh + 1 * DIM * DIM, wl + 1 * DIM * DIM);
    wsplit_t<<<tgrd, tblk>>>(Wv, wh + 2 * DIM * DIM, wl + 2 * DIM * DIM);
    wsplit_t<<<tgrd, tblk>>>(Wf, wh + 3 * DIM * DIM, wl + 3 * DIM * DIM);

    gemm_mma_split<<<ggrd, gblk>>>(xh, xl, wh + 0 * DIM * DIM,
                                   wl + 0 * DIM * DIM, bq, Qp);
    gemm_mma_split<<<ggrd, gblk>>>(xh, xl, wh + 1 * DIM * DIM,
                                   wl + 1 * DIM * DIM, bk, Kp);
    gemm_mma_split<<<ggrd, gblk>>>(xh, xl, wh + 2 * DIM * DIM,
                                   wl + 2 * DIM * DIM, bv, Vp);

    split_f32<<<n4 / 256, 256>>>((const float4*)Qp, (uint2*)qh, (uint2*)ql, ATTN_SCALE);
    split_f32<<<n4 / 256, 256>>>((const float4*)Kp, (uint2*)kh, (uint2*)kl, 1.f);
    split_f32<<<n4 / 256, 256>>>((const float4*)Vp, (uint2*)vh, (uint2*)vl, 1.f);

    dim3 attn_grid(SEQ / 128, BSZ * NH), attn_blk(256);
    attn_mma<<<attn_grid, attn_blk>>>(qh, ql, kh, kl, vh, vl, mask, Ap);

    split_f32<<<n4 / 256, 256>>>((const float4*)Ap, (uint2*)ah, (uint2*)al, 1.f);
    gemm_mma_split<<<ggrd, gblk>>>(ah, al, wh + 3 * DIM * DIM,
                                   wl + 3 * DIM * DIM, bf, out);
}

// round 14
// speedup vs baseline: 3.0606x; 1.2905x over previous
#include <cuda_runtime.h>
#include <cuda_bf16.h>
#include <math_constants.h>
#include <cstdint>

#define BSZ 4
#define SEQ 2048
#define DIM 1024
#define NH  16
#define DK  64
#define ATTN_SCALE 0.125f
#define MTOT (BSZ*SEQ)   // 8192

// ---------------- scratch (device globals: allocation-guard safe) ----------
__device__ float g_Q[MTOT*DIM];
__device__ float g_K[MTOT*DIM];
__device__ float g_V[MTOT*DIM];
__device__ float g_A[MTOT*DIM];
__device__ __nv_bfloat16 g_xh[MTOT*DIM];
__device__ __nv_bfloat16 g_xl[MTOT*DIM];
__device__ __nv_bfloat16 g_ah[MTOT*DIM];
__device__ __nv_bfloat16 g_al[MTOT*DIM];
__device__ __nv_bfloat16 g_qh[MTOT*DIM];
__device__ __nv_bfloat16 g_ql[MTOT*DIM];
__device__ __nv_bfloat16 g_kh[MTOT*DIM];
__device__ __nv_bfloat16 g_kl[MTOT*DIM];
__device__ __nv_bfloat16 g_vh[MTOT*DIM];
__device__ __nv_bfloat16 g_vl[MTOT*DIM];
__device__ __nv_bfloat16 g_wh[4][DIM*DIM];   // W^T hi  [n][k]
__device__ __nv_bfloat16 g_wl[4][DIM*DIM];   // W^T lo  [n][k]

// ---------------- PTX helpers ----------------------------------------------
__device__ __forceinline__ uint32_t smem_u32(const void* p) {
    uint32_t a;
    asm("{ .reg .u64 t; cvta.to.shared.u64 t, %1; cvt.u32.u64 %0, t; }"
        : "=r"(a) : "l"(p));
    return a;
}

__device__ __forceinline__ void cpasync16(uint32_t dst, const void* src) {
    asm volatile("cp.async.cg.shared.global [%0], [%1], 16;"
        :: "r"(dst), "l"(src) : "memory");
}

__device__ __forceinline__ void ldmat4(uint32_t* r, uint32_t addr) {
    asm volatile("ldmatrix.sync.aligned.m8n8.x4.shared.b16 {%0,%1,%2,%3}, [%4];"
        : "=r"(r[0]), "=r"(r[1]), "=r"(r[2]), "=r"(r[3]) : "r"(addr));
}

__device__ __forceinline__ void ldmat4t(uint32_t* r, uint32_t addr) {
    asm volatile("ldmatrix.sync.aligned.m8n8.x4.trans.shared.b16 {%0,%1,%2,%3}, [%4];"
        : "=r"(r[0]), "=r"(r[1]), "=r"(r[2]), "=r"(r[3]) : "r"(addr));
}

// D (fp32) += A (bf16) * B (bf16), m16n8k16
__device__ __forceinline__ void mma_bf16(float* d, const uint32_t* a, const uint32_t* b) {
    asm volatile("mma.sync.aligned.m16n8k16.row.col.f32.bf16.bf16.f32 "
        "{%0,%1,%2,%3}, {%4,%5,%6,%7}, {%8,%9}, {%0,%1,%2,%3};"
        : "+f"(d[0]), "+f"(d[1]), "+f"(d[2]), "+f"(d[3])
        : "r"(a[0]), "r"(a[1]), "r"(a[2]), "r"(a[3]), "r"(b[0]), "r"(b[1]));
}

// pack two f32 -> bf16x2 register {hi, lo}
__device__ __forceinline__ uint32_t cvt2(float hi, float lo) {
    uint32_t r;
    asm("cvt.rn.bf16x2.f32 %0, %1, %2;" : "=r"(r) : "f"(hi), "f"(lo));
    return r;
}

// ---------------------------------------------------------------------------
// Split fp32*scale -> bf16 hi + bf16 lo
// ---------------------------------------------------------------------------
__device__ __forceinline__ uint32_t bfpack(__nv_bfloat16 a, __nv_bfloat16 b) {
    __nv_bfloat162 t = __halves2bfloat162(a, b);
    return *reinterpret_cast<uint32_t*>(&t);
}

__global__ __launch_bounds__(256) void split_f32(
    const float4* __restrict__ in, uint2* __restrict__ hi, uint2* __restrict__ lo,
    float scale)
{
    const int i = blockIdx.x * 256 + threadIdx.x;
    float4 v = in[i];
    v.x *= scale; v.y *= scale; v.z *= scale; v.w *= scale;
    __nv_bfloat16 hx = __float2bfloat16(v.x);
    __nv_bfloat16 hy = __float2bfloat16(v.y);
    __nv_bfloat16 hz = __float2bfloat16(v.z);
    __nv_bfloat16 hw = __float2bfloat16(v.w);
    __nv_bfloat16 lx = __float2bfloat16(v.x - __bfloat162float(hx));
    __nv_bfloat16 ly = __float2bfloat16(v.y - __bfloat162float(hy));
    __nv_bfloat16 lz = __float2bfloat16(v.z - __bfloat162float(hz));
    __nv_bfloat16 lw = __float2bfloat16(v.w - __bfloat162float(hw));
    hi[i] = make_uint2(bfpack(hx, hy), bfpack(hz, hw));
    lo[i] = make_uint2(bfpack(lx, ly), bfpack(lz, lw));
}

// ---------------------------------------------------------------------------
// Transpose + split W[k][n] -> Wt_hi/lo [n][k]
// ---------------------------------------------------------------------------
__global__ __launch_bounds__(256) void wsplit_t(
    const float* __restrict__ W, __nv_bfloat16* __restrict__ th,
    __nv_bfloat16* __restrict__ tl)
{
    __shared__ float s[32][33];
    const int tx = threadIdx.x, ty = threadIdx.y;
    const int bx = blockIdx.x, by = blockIdx.y;
    #pragma unroll
    for (int j = 0; j < 32; j += 8)
        s[ty + j][tx] = W[(by * 32 + ty + j) * DIM + bx * 32 + tx];
    __syncthreads();
    #pragma unroll
    for (int j = 0; j < 32; j += 8) {
        float v = s[tx][ty + j];
        __nv_bfloat16 h = __float2bfloat16(v);
        int o = (bx * 32 + ty + j) * DIM + by * 32 + tx;
        th[o] = h;
        tl[o] = __float2bfloat16(v - __bfloat162float(h));
    }
}

// ---------------------------------------------------------------------------
// HMMA split-bf16 GEMM, 3-stage pipeline, 48KB static smem.
// Tiles: 128 rows x 32B (16 bf16), XOR-swizzled in 16B units:
//   phys = row*32 + ((u ^ ((row>>2)&1)) << 4)
// (all ldmatrix phases hit 8 distinct 16B banks mod 128B).
// Loop: wait(chunk c) -> barrier -> prefetch(c+2) -> compute. 1 barrier/chunk.
// ---------------------------------------------------------------------------
#define GBK    16
#define GNCH   (DIM / GBK)         // 64 chunks
#define GTILE  4096                // 128 rows * 32 B
#define GSTAGE (4 * GTILE)         // Ah | Al | Bh | Bl

__global__ __launch_bounds__(256) void gemm_mma_split(
    const __nv_bfloat16* __restrict__ Ah, const __nv_bfloat16* __restrict__ Al,
    const __nv_bfloat16* __restrict__ Bh, const __nv_bfloat16* __restrict__ Bl,
    const float* __restrict__ bias, float* __restrict__ C)
{
    __shared__ char smem[3][4][GTILE];   // [stage][Ah,Al,Bh,Bl][tile]

    const int tid  = threadIdx.x;
    const int lane = tid & 31, wid = tid >> 5;
    const int m0 = blockIdx.y * 128, n0 = blockIdx.x * 128;
    const int wm = (wid & 3) * 32;       // warp m offset in tile
    const int wn = (wid >> 2) * 64;      // warp n offset in tile

    // cp.async assignment: thread t -> row t/2, 16B k-half t%2 (per tile)
    const int trow = tid >> 1, thalf = tid & 1;
    const char* gsrc0 = (const char*)(Ah + (size_t)(m0 + trow) * DIM) + thalf * 16;
    const char* gsrc1 = (const char*)(Al + (size_t)(m0 + trow) * DIM) + thalf * 16;
    const char* gsrc2 = (const char*)(Bh + (size_t)(n0 + trow) * DIM) + thalf * 16;
    const char* gsrc3 = (const char*)(Bl + (size_t)(n0 + trow) * DIM) + thalf * 16;
    const uint32_t doff =
        (uint32_t)(trow * 32 + ((thalf ^ ((trow >> 2) & 1)) << 4));
    const uint32_t sb = smem_u32(&smem[0][0][0]);

    // ldmatrix relative offsets (within a tile), swizzle folded in
    uint32_t aoff[2];
    #pragma unroll
    for (int mt = 0; mt < 2; mt++) {
        const int row = wm + mt * 16 + (lane & 15);
        aoff[mt] = (uint32_t)(row * 32 + (((lane >> 4) ^ ((row >> 2) & 1)) << 4));
    }
    uint32_t boff[4];
    #pragma unroll
    for (int p = 0; p < 4; p++) {
        const int row = wn + p * 16 + ((lane >> 4) << 3) + (lane & 7);
        boff[p] = (uint32_t)(row * 32 + ((((lane >> 3) & 1) ^ ((row >> 2) & 1)) << 4));
    }

    float acc[2][8][4];
    #pragma unroll
    for (int mt = 0; mt < 2; mt++)
        #pragma unroll
        for (int nt = 0; nt < 8; nt++)
            #pragma unroll
            for (int i = 0; i < 4; i++) acc[mt][nt][i] = 0.f;

    auto load_chunk = [&](int c) {
        const uint32_t base = sb + (uint32_t)(c % 3) * GSTAGE + doff;
        const int kb = c * 32;           // 16 bf16 = 32 bytes along K
        cpasync16(base + 0 * GTILE, gsrc0 + kb);
        cpasync16(base + 1 * GTILE, gsrc1 + kb);
        cpasync16(base + 2 * GTILE, gsrc2 + kb);
        cpasync16(base + 3 * GTILE, gsrc3 + kb);
        asm volatile("cp.async.commit_group;" ::: "memory");
    };

    load_chunk(0);
    load_chunk(1);

    #pragma unroll 1
    for (int c = 0; c < GNCH; c++) {
        if (c < GNCH - 1) asm volatile("cp.async.wait_group 1;" ::: "memory");
        else              asm volatile("cp.async.wait_group 0;" ::: "memory");
        __syncthreads();                 // all warps done with slot (c-1)%3
        if (c + 2 < GNCH) load_chunk(c + 2);   // writes slot (c-1)%3

        const uint32_t tb = sb + (uint32_t)(c % 3) * GSTAGE;
        uint32_t af[2][2][4];
        uint32_t bf[2][8][2];
        #pragma unroll
        for (int h = 0; h < 2; h++) {
            const uint32_t ta = tb + h * GTILE;
            #pragma unroll
            for (int mt = 0; mt < 2; mt++) ldmat4(af[h][mt], ta + aoff[mt]);
            const uint32_t tB = tb + (2 + h) * GTILE;
            #pragma unroll
            for (int p = 0; p < 4; p++) {
                uint32_t r[4];
                ldmat4(r, tB + boff[p]);
                bf[h][p * 2 + 0][0] = r[0]; bf[h][p * 2 + 0][1] = r[1];
                bf[h][p * 2 + 1][0] = r[2]; bf[h][p * 2 + 1][1] = r[3];
            }
        }

        #pragma unroll
        for (int mt = 0; mt < 2; mt++)
            #pragma unroll
            for (int nt = 0; nt < 8; nt++)
                mma_bf16(acc[mt][nt], af[0][mt], bf[0][nt]);
        #pragma unroll
        for (int mt = 0; mt < 2; mt++)
            #pragma unroll
            for (int nt = 0; nt < 8; nt++)
                mma_bf16(acc[mt][nt], af[0][mt], bf[1][nt]);
        #pragma unroll
        for (int mt = 0; mt < 2; mt++)
            #pragma unroll
            for (int nt = 0; nt < 8; nt++)
                mma_bf16(acc[mt][nt], af[1][mt], bf[0][nt]);
    }

    const int er = lane >> 2, ec = (lane & 3) * 2;
    #pragma unroll
    for (int mt = 0; mt < 2; mt++) {
        const int row = m0 + wm + mt * 16 + er;
        #pragma unroll
        for (int nt = 0; nt < 8; nt++) {
            const int col = n0 + wn + nt * 8 + ec;
            const float b0 = bias[col], b1 = bias[col + 1];
            float2 v0 = make_float2(acc[mt][nt][0] + b0, acc[mt][nt][1] + b1);
            float2 v1 = make_float2(acc[mt][nt][2] + b0, acc[mt][nt][3] + b1);
            *(float2*)&C[(size_t)row * DIM + col]       = v0;
            *(float2*)&C[(size_t)(row + 8) * DIM + col] = v1;
        }
    }
}

// ---------------------------------------------------------------------------
// Flash attention via mma.sync bf16 hi/lo split (R13 numerics, restructured
// sync: wait -> barrier -> prefetch -> compute; 2 barriers/kt instead of 4).
// ---------------------------------------------------------------------------
#define ANKT (SEQ / 64)            // 32 key tiles

__global__ __launch_bounds__(256) void attn_mma(
    const __nv_bfloat16* __restrict__ qh, const __nv_bfloat16* __restrict__ ql,
    const __nv_bfloat16* __restrict__ kh, const __nv_bfloat16* __restrict__ kl,
    const __nv_bfloat16* __restrict__ vh, const __nv_bfloat16* __restrict__ vl,
    const int* __restrict__ mask, float* __restrict__ gO)
{
    __shared__ char ring[3][16384];

    const int tid = threadIdx.x, lane = tid & 31, w = tid >> 5;
    const int q0 = blockIdx.x * 128;
    const int bh_ = blockIdx.y;
    const int b = bh_ >> 4, h = bh_ & 15;
    const int er = lane >> 2, qq = lane & 3;

    uint32_t rb[3];
    rb[0] = smem_u32(ring[0]); rb[1] = smem_u32(ring[1]); rb[2] = smem_u32(ring[2]);

    // ---- stage Q (Qh -> slot0, Ql -> slot1), swizzled -----------------------
    {
        const int row = tid >> 1;
        const int u0 = (tid & 1) * 4;
        const char* sh = (const char*)(qh + (size_t)(b * SEQ + q0 + row) * DIM + h * DK);
        const char* sl = (const char*)(ql + (size_t)(b * SEQ + q0 + row) * DIM + h * DK);
        #pragma unroll
        for (int u = 0; u < 4; u++) {
            const uint32_t off = (uint32_t)(row * 128 + (((u0 + u) ^ (row & 7)) << 4));
            cpasync16(rb[0] + off, sh + (u0 + u) * 16);
            cpasync16(rb[1] + off, sl + (u0 + u) * 16);
        }
        asm volatile("cp.async.commit_group;" ::: "memory");
        asm volatile("cp.async.wait_group 0;" ::: "memory");
        __syncthreads();
    }

    // Q fragments: [h/l][kstep][4]
    uint32_t qf[2][4][4];
    {
        const int row = w * 16 + (lane & 15);
        const int rx = row & 7;
        #pragma unroll
        for (int ks = 0; ks < 4; ks++) {
            const uint32_t addr = (uint32_t)(row * 128 + (((2 * ks + (lane >> 4)) ^ rx) << 4));
            ldmat4(qf[0][ks], rb[0] + addr);
            ldmat4(qf[1][ks], rb[1] + addr);
        }
    }
    __syncthreads();   // ring slots free for K/V now

    // lane-constant address parts
    const int kx = lane & 7;
    const uint32_t kkbase = (uint32_t)(((((lane >> 4) << 3) + (lane & 7))) * 128);
    const uint32_t kvbase = (uint32_t)(((((lane >> 3) & 1) << 3) + (lane & 7)) * 128);
    uint32_t xk[4], xv[4];
    #pragma unroll
    for (int ks = 0; ks < 4; ks++)
        xk[ks] = (uint32_t)((((2 * ks + ((lane >> 3) & 1)) ^ kx)) << 4);
    #pragma unroll
    for (int t = 0; t < 4; t++)
        xv[t] = (uint32_t)((((2 * t + (lane >> 4)) ^ kx)) << 4);

    // resource loader: r even -> K tile r/2, r odd -> V tile r/2; slot r%3
    const int lrow = tid >> 2;
    const int lu0 = (tid & 3) * 2;
    auto load_res = [&](int r) {
        const int kt = r >> 1;
        const __nv_bfloat16* sh = (r & 1) ? vh : kh;
        const __nv_bfloat16* sl = (r & 1) ? vl : kl;
        const char* gh = (const char*)(sh + (size_t)(b * SEQ + kt * 64 + lrow) * DIM + h * DK);
        const char* gl = (const char*)(sl + (size_t)(b * SEQ + kt * 64 + lrow) * DIM + h * DK);
        const uint32_t base = rb[r % 3] + (uint32_t)(lrow * 128);
        #pragma unroll
        for (int u = 0; u < 2; u++) {
            const uint32_t off = (uint32_t)((((lu0 + u) ^ (lrow & 7)) << 4));
            cpasync16(base + off,        gh + (lu0 + u) * 16);
            cpasync16(base + 8192 + off, gl + (lu0 + u) * 16);
        }
        asm volatile("cp.async.commit_group;" ::: "memory");
    };

    float m[2] = {-CUDART_INF_F, -CUDART_INF_F};
    float l[2] = {0.f, 0.f};
    float oacc[8][4];
    #pragma unroll
    for (int n = 0; n < 8; n++)
        #pragma unroll
        for (int i = 0; i < 4; i++) oacc[n][i] = 0.f;

    uint32_t phx[8], phy[8], plx[8], ply[8];
    const int* maskB = mask + b * SEQ;

    load_res(0);
    load_res(1);

    #pragma unroll 1
    for (int kt = 0; kt < ANKT; kt++) {
        // ================= S step (resource 2kt, slot (2kt)%3) ==============
        asm volatile("cp.async.wait_group 1;" ::: "memory");  // res 2kt done
        __syncthreads();                       // all warps done with V(kt-1) slot
        if (kt + 1 < ANKT) load_res(2 * kt + 2);   // writes V(kt-1)'s slot
        {
            const uint32_t sb = rb[(2 * kt) % 3];
            float sacc[8][4];
            #pragma unroll
            for (int n = 0; n < 8; n++)
                #pragma unroll
                for (int i = 0; i < 4; i++) sacc[n][i] = 0.f;

            #pragma unroll
            for (int ks = 0; ks < 4; ks++) {
                uint32_t bf_[4][4];
                #pragma unroll
                for (int p = 0; p < 4; p++)
                    ldmat4(bf_[p], sb + p * 2048 + kkbase + xk[ks]);
                #pragma unroll
                for (int nt = 0; nt < 8; nt++)
                    mma_bf16(sacc[nt], qf[0][ks], &bf_[nt >> 1][(nt & 1) * 2]);
                #pragma unroll
                for (int nt = 0; nt < 8; nt++)
                    mma_bf16(sacc[nt], qf[1][ks], &bf_[nt >> 1][(nt & 1) * 2]);
                #pragma unroll
                for (int p = 0; p < 4; p++)
                    ldmat4(bf_[p], sb + 8192 + p * 2048 + kkbase + xk[ks]);
                #pragma unroll
                for (int nt = 0; nt < 8; nt++)
                    mma_bf16(sacc[nt], qf[0][ks], &bf_[nt >> 1][(nt & 1) * 2]);
            }

            // mask (exactly -1e30, as reference), row max
            float mx0 = -CUDART_INF_F, mx1 = -CUDART_INF_F;
            #pragma unroll
            for (int nt = 0; nt < 8; nt++) {
                int2 mk = *(const int2*)&maskB[kt * 64 + nt * 8 + 2 * qq];
                if (mk.x) { sacc[nt][0] = -1e30f; sacc[nt][2] = -1e30f; }
                if (mk.y) { sacc[nt][1] = -1e30f; sacc[nt][3] = -1e30f; }
                mx0 = fmaxf(mx0, fmaxf(sacc[nt][0], sacc[nt][1]));
                mx1 = fmaxf(mx1, fmaxf(sacc[nt][2], sacc[nt][3]));
            }
            mx0 = fmaxf(mx0, __shfl_xor_sync(0xffffffffu, mx0, 1));
            mx0 = fmaxf(mx0, __shfl_xor_sync(0xffffffffu, mx0, 2));
            mx1 = fmaxf(mx1, __shfl_xor_sync(0xffffffffu, mx1, 1));
            mx1 = fmaxf(mx1, __shfl_xor_sync(0xffffffffu, mx1, 2));

            const float mn0 = fmaxf(m[0], mx0), mn1 = fmaxf(m[1], mx1);
            const float al0 = __expf(m[0] - mn0), al1 = __expf(m[1] - mn1);
            m[0] = mn0; m[1] = mn1;

            float rs0 = 0.f, rs1 = 0.f;
            #pragma unroll
            for (int nt = 0; nt < 8; nt++) {
                const float p0 = __expf(sacc[nt][0] - mn0);
                const float p1 = __expf(sacc[nt][1] - mn0);
                const float p2 = __expf(sacc[nt][2] - mn1);
                const float p3 = __expf(sacc[nt][3] - mn1);
                rs0 += p0 + p1; rs1 += p2 + p3;
                const uint32_t hA = cvt2(p1, p0);
                const uint32_t hB = cvt2(p3, p2);
                phx[nt] = hA; phy[nt] = hB;
                plx[nt] = cvt2(p1 - __uint_as_float(hA & 0xffff0000u),
                               p0 - __uint_as_float(hA << 16));
                ply[nt] = cvt2(p3 - __uint_as_float(hB & 0xffff0000u),
                               p2 - __uint_as_float(hB << 16));
            }
            rs0 += __shfl_xor_sync(0xffffffffu, rs0, 1);
            rs0 += __shfl_xor_sync(0xffffffffu, rs0, 2);
            rs1 += __shfl_xor_sync(0xffffffffu, rs1, 1);
            rs1 += __shfl_xor_sync(0xffffffffu, rs1, 2);
            l[0] = l[0] * al0 + rs0;
            l[1] = l[1] * al1 + rs1;

            #pragma unroll
            for (int n = 0; n < 8; n++) {
                oacc[n][0] *= al0; oacc[n][1] *= al0;
                oacc[n][2] *= al1; oacc[n][3] *= al1;
            }
        }

        // ================= PV step (resource 2kt+1, slot (2kt+1)%3) =========
        if (kt + 1 < ANKT) asm volatile("cp.async.wait_group 1;" ::: "memory");
        else               asm volatile("cp.async.wait_group 0;" ::: "memory");
        __syncthreads();                       // all warps done with K(kt) slot
        if (kt + 1 < ANKT) load_res(2 * kt + 3);   // writes K(kt)'s slot
        {
            const uint32_t sb = rb[(2 * kt + 1) % 3];
            #pragma unroll
            for (int j = 0; j < 4; j++) {
                uint32_t aH[4] = {phx[2 * j], phy[2 * j], phx[2 * j + 1], phy[2 * j + 1]};
                uint32_t aL[4] = {plx[2 * j], ply[2 * j], plx[2 * j + 1], ply[2 * j + 1]};
                uint32_t bv_[4][4];
                #pragma unroll
                for (int t = 0; t < 4; t++)
                    ldmat4t(bv_[t], sb + j * 2048 + kvbase + xv[t]);
                #pragma unroll
                for (int n = 0; n < 8; n++)
                    mma_bf16(oacc[n], aH, &bv_[n >> 1][(n & 1) * 2]);
                #pragma unroll
                for (int n = 0; n < 8; n++)
                    mma_bf16(oacc[n], aL, &bv_[n >> 1][(n & 1) * 2]);
                #pragma unroll
                for (int t = 0; t < 4; t++)
                    ldmat4t(bv_[t], sb + 8192 + j * 2048 + kvbase + xv[t]);
                #pragma unroll
                for (int n = 0; n < 8; n++)
                    mma_bf16(oacc[n], aH, &bv_[n >> 1][(n & 1) * 2]);
            }
        }
    }

    // ---- epilogue ----------------------------------------------------------
    const float inv0 = 1.f / l[0], inv1 = 1.f / l[1];
    const int row0 = b * SEQ + q0 + w * 16 + er;
    float* o0 = gO + (size_t)row0 * DIM + h * DK + 2 * qq;
    float* o1 = o0 + (size_t)8 * DIM;
    #pragma unroll
    for (int n = 0; n < 8; n++) {
        *(float2*)(o0 + n * 8) = make_float2(oacc[n][0] * inv0, oacc[n][1] * inv0);
        *(float2*)(o1 + n * 8) = make_float2(oacc[n][2] * inv1, oacc[n][3] * inv1);
    }
}

// ---------------------------------------------------------------------------
extern "C" void kernel_launch(void* const* d_in, const int* in_sizes, int n_in,
                              void* d_out, int out_size)
{
    const float* x    = (const float*)d_in[0];
    const int*   mask = (const int*)  d_in[1];
    const float* Wq   = (const float*)d_in[2];
    const float* bq   = (const float*)d_in[3];
    const float* Wk   = (const float*)d_in[4];
    const float* bk   = (const float*)d_in[5];
    const float* Wv   = (const float*)d_in[6];
    const float* bv   = (const float*)d_in[7];
    const float* Wf   = (const float*)d_in[8];
    const float* bf   = (const float*)d_in[9];
    float* out = (float*)d_out;

    float *Qp, *Kp, *Vp, *Ap;
    cudaGetSymbolAddress((void**)&Qp, g_Q);
    cudaGetSymbolAddress((void**)&Kp, g_K);
    cudaGetSymbolAddress((void**)&Vp, g_V);
    cudaGetSymbolAddress((void**)&Ap, g_A);
    __nv_bfloat16 *xh, *xl, *ah, *al, *wh, *wl, *qh, *ql, *kh, *kl, *vh, *vl;
    cudaGetSymbolAddress((void**)&xh, g_xh);
    cudaGetSymbolAddress((void**)&xl, g_xl);
    cudaGetSymbolAddress((void**)&ah, g_ah);
    cudaGetSymbolAddress((void**)&al, g_al);
    cudaGetSymbolAddress((void**)&wh, g_wh);
    cudaGetSymbolAddress((void**)&wl, g_wl);
    cudaGetSymbolAddress((void**)&qh, g_qh);
    cudaGetSymbolAddress((void**)&ql, g_ql);
    cudaGetSymbolAddress((void**)&kh, g_kh);
    cudaGetSymbolAddress((void**)&kl, g_kl);
    cudaGetSymbolAddress((void**)&vh, g_vh);
    cudaGetSymbolAddress((void**)&vl, g_vl);

    const int n4 = MTOT * DIM / 4;
    dim3 tblk(32, 8), tgrd(32, 32);
    dim3 ggrd(8, 64), gblk(256);

    split_f32<<<n4 / 256, 256>>>((const float4*)x, (uint2*)xh, (uint2*)xl, 1.f);
    wsplit_t<<<tgrd, tblk>>>(Wq, wh + 0 * DIM * DIM, wl + 0 * DIM * DIM);
    wsplit_t<<<tgrd, tblk>>>(Wk, wh + 1 * DIM * DIM, wl + 1 * DIM * DIM);
    wsplit_t<<<tgrd, tblk>>>(Wv, wh + 2 * DIM * DIM, wl + 2 * DIM * DIM);
    wsplit_t<<<tgrd, tblk>>>(Wf, wh + 3 * DIM * DIM, wl + 3 * DIM * DIM);

    gemm_mma_split<<<ggrd, gblk>>>(xh, xl, wh + 0 * DIM * DIM,
                                   wl + 0 * DIM * DIM, bq, Qp);
    gemm_mma_split<<<ggrd, gblk>>>(xh, xl, wh + 1 * DIM * DIM,
                                   wl + 1 * DIM * DIM, bk, Kp);
    gemm_mma_split<<<ggrd, gblk>>>(xh, xl, wh + 2 * DIM * DIM,
                                   wl + 2 * DIM * DIM, bv, Vp);

    split_f32<<<n4 / 256, 256>>>((const float4*)Qp, (uint2*)qh, (uint2*)ql, ATTN_SCALE);
    split_f32<<<n4 / 256, 256>>>((const float4*)Kp, (uint2*)kh, (uint2*)kl, 1.f);
    split_f32<<<n4 / 256, 256>>>((const float4*)Vp, (uint2*)vh, (uint2*)vl, 1.f);

    dim3 attn_grid(SEQ / 128, BSZ * NH), attn_blk(256);
    attn_mma<<<attn_grid, attn_blk>>>(qh, ql, kh, kl, vh, vl, mask, Ap);

    split_f32<<<n4 / 256, 256>>>((const float4*)Ap, (uint2*)ah, (uint2*)al, 1.f);
    gemm_mma_split<<<ggrd, gblk>>>(ah, al, wh + 3 * DIM * DIM,
                                   wl + 3 * DIM * DIM, bf, out);
}

// round 15
// speedup vs baseline: 3.1483x; 1.0287x over previous
#include <cuda_runtime.h>
#include <cuda_bf16.h>
#include <math_constants.h>
#include <cstdint>

#define BSZ 4
#define SEQ 2048
#define DIM 1024
#define NH  16
#define DK  64
#define ATTN_SCALE 0.125f
#define MTOT (BSZ*SEQ)   // 8192

// ---------------- scratch (device globals: allocation-guard safe) ----------
__device__ __nv_bfloat16 g_xh[MTOT*DIM];
__device__ __nv_bfloat16 g_xl[MTOT*DIM];
__device__ __nv_bfloat16 g_ah[MTOT*DIM];
__device__ __nv_bfloat16 g_al[MTOT*DIM];
__device__ __nv_bfloat16 g_qh[MTOT*DIM];
__device__ __nv_bfloat16 g_ql[MTOT*DIM];
__device__ __nv_bfloat16 g_kh[MTOT*DIM];
__device__ __nv_bfloat16 g_kl[MTOT*DIM];
__device__ __nv_bfloat16 g_vh[MTOT*DIM];
__device__ __nv_bfloat16 g_vl[MTOT*DIM];
__device__ __nv_bfloat16 g_wh[4][DIM*DIM];   // W^T hi  [n][k]
__device__ __nv_bfloat16 g_wl[4][DIM*DIM];   // W^T lo  [n][k]

// ---------------- PTX helpers ----------------------------------------------
__device__ __forceinline__ uint32_t smem_u32(const void* p) {
    uint32_t a;
    asm("{ .reg .u64 t; cvta.to.shared.u64 t, %1; cvt.u32.u64 %0, t; }"
        : "=r"(a) : "l"(p));
    return a;
}

__device__ __forceinline__ void cpasync16(uint32_t dst, const void* src) {
    asm volatile("cp.async.cg.shared.global [%0], [%1], 16;"
        :: "r"(dst), "l"(src) : "memory");
}

__device__ __forceinline__ void ldmat4(uint32_t* r, uint32_t addr) {
    asm volatile("ldmatrix.sync.aligned.m8n8.x4.shared.b16 {%0,%1,%2,%3}, [%4];"
        : "=r"(r[0]), "=r"(r[1]), "=r"(r[2]), "=r"(r[3]) : "r"(addr));
}

__device__ __forceinline__ void ldmat4t(uint32_t* r, uint32_t addr) {
    asm volatile("ldmatrix.sync.aligned.m8n8.x4.trans.shared.b16 {%0,%1,%2,%3}, [%4];"
        : "=r"(r[0]), "=r"(r[1]), "=r"(r[2]), "=r"(r[3]) : "r"(addr));
}

// D (fp32) += A (bf16) * B (bf16), m16n8k16
__device__ __forceinline__ void mma_bf16(float* d, const uint32_t* a, const uint32_t* b) {
    asm volatile("mma.sync.aligned.m16n8k16.row.col.f32.bf16.bf16.f32 "
        "{%0,%1,%2,%3}, {%4,%5,%6,%7}, {%8,%9}, {%0,%1,%2,%3};"
        : "+f"(d[0]), "+f"(d[1]), "+f"(d[2]), "+f"(d[3])
        : "r"(a[0]), "r"(a[1]), "r"(a[2]), "r"(a[3]), "r"(b[0]), "r"(b[1]));
}

// pack two f32 -> bf16x2 register {hi, lo}
__device__ __forceinline__ uint32_t cvt2(float hi, float lo) {
    uint32_t r;
    asm("cvt.rn.bf16x2.f32 %0, %1, %2;" : "=r"(r) : "f"(hi), "f"(lo));
    return r;
}

// split two fp32 into bf16-hi pair and bf16-lo pair (packed bf16x2 each)
__device__ __forceinline__ void split2(float v0, float v1, uint32_t& hp, uint32_t& lp) {
    hp = cvt2(v1, v0);   // {lo-half = v0, hi-half = v1}
    lp = cvt2(v1 - __uint_as_float(hp & 0xffff0000u),
              v0 - __uint_as_float(hp << 16));
}

// ---------------------------------------------------------------------------
// Split fp32*scale -> bf16 hi + bf16 lo (used only for the input x)
// ---------------------------------------------------------------------------
__device__ __forceinline__ uint32_t bfpack(__nv_bfloat16 a, __nv_bfloat16 b) {
    __nv_bfloat162 t = __halves2bfloat162(a, b);
    return *reinterpret_cast<uint32_t*>(&t);
}

__global__ __launch_bounds__(256) void split_f32(
    const float4* __restrict__ in, uint2* __restrict__ hi, uint2* __restrict__ lo,
    float scale)
{
    const int i = blockIdx.x * 256 + threadIdx.x;
    float4 v = in[i];
    v.x *= scale; v.y *= scale; v.z *= scale; v.w *= scale;
    __nv_bfloat16 hx = __float2bfloat16(v.x);
    __nv_bfloat16 hy = __float2bfloat16(v.y);
    __nv_bfloat16 hz = __float2bfloat16(v.z);
    __nv_bfloat16 hw = __float2bfloat16(v.w);
    __nv_bfloat16 lx = __float2bfloat16(v.x - __bfloat162float(hx));
    __nv_bfloat16 ly = __float2bfloat16(v.y - __bfloat162float(hy));
    __nv_bfloat16 lz = __float2bfloat16(v.z - __bfloat162float(hz));
    __nv_bfloat16 lw = __float2bfloat16(v.w - __bfloat162float(hw));
    hi[i] = make_uint2(bfpack(hx, hy), bfpack(hz, hw));
    lo[i] = make_uint2(bfpack(lx, ly), bfpack(lz, lw));
}

// ---------------------------------------------------------------------------
// Transpose + split W[k][n] -> Wt_hi/lo [n][k]
// ---------------------------------------------------------------------------
__global__ __launch_bounds__(256) void wsplit_t(
    const float* __restrict__ W, __nv_bfloat16* __restrict__ th,
    __nv_bfloat16* __restrict__ tl)
{
    __shared__ float s[32][33];
    const int tx = threadIdx.x, ty = threadIdx.y;
    const int bx = blockIdx.x, by = blockIdx.y;
    #pragma unroll
    for (int j = 0; j < 32; j += 8)
        s[ty + j][tx] = W[(by * 32 + ty + j) * DIM + bx * 32 + tx];
    __syncthreads();
    #pragma unroll
    for (int j = 0; j < 32; j += 8) {
        float v = s[tx][ty + j];
        __nv_bfloat16 h = __float2bfloat16(v);
        int o = (bx * 32 + ty + j) * DIM + by * 32 + tx;
        th[o] = h;
        tl[o] = __float2bfloat16(v - __bfloat162float(h));
    }
}

// ---------------------------------------------------------------------------
// HMMA split-bf16 GEMM, 3-stage pipeline, 48KB static smem (R14 mainloop).
// Epilogue: either fp32 C (+bias), or fused hi/lo bf16 split of
// (acc+bias)*scale — identical arithmetic to the old split_f32 pass.
// ---------------------------------------------------------------------------
#define GBK    16
#define GNCH   (DIM / GBK)         // 64 chunks
#define GTILE  4096                // 128 rows * 32 B
#define GSTAGE (4 * GTILE)         // Ah | Al | Bh | Bl

__global__ __launch_bounds__(256) void gemm_mma_split(
    const __nv_bfloat16* __restrict__ Ah, const __nv_bfloat16* __restrict__ Al,
    const __nv_bfloat16* __restrict__ Bh, const __nv_bfloat16* __restrict__ Bl,
    const float* __restrict__ bias, float* __restrict__ Cf32,
    __nv_bfloat16* __restrict__ Chi, __nv_bfloat16* __restrict__ Clo,
    float scale)
{
    __shared__ char smem[3][4][GTILE];   // [stage][Ah,Al,Bh,Bl][tile]

    const int tid  = threadIdx.x;
    const int lane = tid & 31, wid = tid >> 5;
    const int m0 = blockIdx.y * 128, n0 = blockIdx.x * 128;
    const int wm = (wid & 3) * 32;       // warp m offset in tile
    const int wn = (wid >> 2) * 64;      // warp n offset in tile

    // cp.async assignment: thread t -> row t/2, 16B k-half t%2 (per tile)
    const int trow = tid >> 1, thalf = tid & 1;
    const char* gsrc0 = (const char*)(Ah + (size_t)(m0 + trow) * DIM) + thalf * 16;
    const char* gsrc1 = (const char*)(Al + (size_t)(m0 + trow) * DIM) + thalf * 16;
    const char* gsrc2 = (const char*)(Bh + (size_t)(n0 + trow) * DIM) + thalf * 16;
    const char* gsrc3 = (const char*)(Bl + (size_t)(n0 + trow) * DIM) + thalf * 16;
    const uint32_t doff =
        (uint32_t)(trow * 32 + ((thalf ^ ((trow >> 2) & 1)) << 4));
    const uint32_t sb = smem_u32(&smem[0][0][0]);

    // ldmatrix relative offsets (within a tile), swizzle folded in
    uint32_t aoff[2];
    #pragma unroll
    for (int mt = 0; mt < 2; mt++) {
        const int row = wm + mt * 16 + (lane & 15);
        aoff[mt] = (uint32_t)(row * 32 + (((lane >> 4) ^ ((row >> 2) & 1)) << 4));
    }
    uint32_t boff[4];
    #pragma unroll
    for (int p = 0; p < 4; p++) {
        const int row = wn + p * 16 + ((lane >> 4) << 3) + (lane & 7);
        boff[p] = (uint32_t)(row * 32 + ((((lane >> 3) & 1) ^ ((row >> 2) & 1)) << 4));
    }

    float acc[2][8][4];
    #pragma unroll
    for (int mt = 0; mt < 2; mt++)
        #pragma unroll
        for (int nt = 0; nt < 8; nt++)
            #pragma unroll
            for (int i = 0; i < 4; i++) acc[mt][nt][i] = 0.f;

    auto load_chunk = [&](int c) {
        const uint32_t base = sb + (uint32_t)(c % 3) * GSTAGE + doff;
        const int kb = c * 32;           // 16 bf16 = 32 bytes along K
        cpasync16(base + 0 * GTILE, gsrc0 + kb);
        cpasync16(base + 1 * GTILE, gsrc1 + kb);
        cpasync16(base + 2 * GTILE, gsrc2 + kb);
        cpasync16(base + 3 * GTILE, gsrc3 + kb);
        asm volatile("cp.async.commit_group;" ::: "memory");
    };

    load_chunk(0);
    load_chunk(1);

    #pragma unroll 1
    for (int c = 0; c < GNCH; c++) {
        if (c < GNCH - 1) asm volatile("cp.async.wait_group 1;" ::: "memory");
        else              asm volatile("cp.async.wait_group 0;" ::: "memory");
        __syncthreads();                 // all warps done with slot (c-1)%3
        if (c + 2 < GNCH) load_chunk(c + 2);   // writes slot (c-1)%3

        const uint32_t tb = sb + (uint32_t)(c % 3) * GSTAGE;
        uint32_t af[2][2][4];
        uint32_t bf[2][8][2];
        #pragma unroll
        for (int h = 0; h < 2; h++) {
            const uint32_t ta = tb + h * GTILE;
            #pragma unroll
            for (int mt = 0; mt < 2; mt++) ldmat4(af[h][mt], ta + aoff[mt]);
            const uint32_t tB = tb + (2 + h) * GTILE;
            #pragma unroll
            for (int p = 0; p < 4; p++) {
                uint32_t r[4];
                ldmat4(r, tB + boff[p]);
                bf[h][p * 2 + 0][0] = r[0]; bf[h][p * 2 + 0][1] = r[1];
                bf[h][p * 2 + 1][0] = r[2]; bf[h][p * 2 + 1][1] = r[3];
            }
        }

        #pragma unroll
        for (int mt = 0; mt < 2; mt++)
            #pragma unroll
            for (int nt = 0; nt < 8; nt++)
                mma_bf16(acc[mt][nt], af[0][mt], bf[0][nt]);
        #pragma unroll
        for (int mt = 0; mt < 2; mt++)
            #pragma unroll
            for (int nt = 0; nt < 8; nt++)
                mma_bf16(acc[mt][nt], af[0][mt], bf[1][nt]);
        #pragma unroll
        for (int mt = 0; mt < 2; mt++)
            #pragma unroll
            for (int nt = 0; nt < 8; nt++)
                mma_bf16(acc[mt][nt], af[1][mt], bf[0][nt]);
    }

    // Epilogue: c0,c1 -> (row, col..col+1); c2,c3 -> (row+8, ...)
    const int er = lane >> 2, ec = (lane & 3) * 2;
    #pragma unroll
    for (int mt = 0; mt < 2; mt++) {
        const int row = m0 + wm + mt * 16 + er;
        #pragma unroll
        for (int nt = 0; nt < 8; nt++) {
            const int col = n0 + wn + nt * 8 + ec;
            const float b0 = bias[col], b1 = bias[col + 1];
            const float v00 = acc[mt][nt][0] + b0, v01 = acc[mt][nt][1] + b1;
            const float v10 = acc[mt][nt][2] + b0, v11 = acc[mt][nt][3] + b1;
            if (Cf32) {
                *(float2*)&Cf32[(size_t)row * DIM + col]       = make_float2(v00, v01);
                *(float2*)&Cf32[(size_t)(row + 8) * DIM + col] = make_float2(v10, v11);
            } else {
                uint32_t hp, lp;
                split2(v00 * scale, v01 * scale, hp, lp);
                *(uint32_t*)&Chi[(size_t)row * DIM + col] = hp;
                *(uint32_t*)&Clo[(size_t)row * DIM + col] = lp;
                split2(v10 * scale, v11 * scale, hp, lp);
                *(uint32_t*)&Chi[(size_t)(row + 8) * DIM + col] = hp;
                *(uint32_t*)&Clo[(size_t)(row + 8) * DIM + col] = lp;
            }
        }
    }
}

// ---------------------------------------------------------------------------
// Flash attention via mma.sync bf16 hi/lo split (R14 mainloop).
// Epilogue: fused hi/lo bf16 split of O (identical to old split_f32 pass).
// ---------------------------------------------------------------------------
#define ANKT (SEQ / 64)            // 32 key tiles

__global__ __launch_bounds__(256) void attn_mma(
    const __nv_bfloat16* __restrict__ qh, const __nv_bfloat16* __restrict__ ql,
    const __nv_bfloat16* __restrict__ kh, const __nv_bfloat16* __restrict__ kl,
    const __nv_bfloat16* __restrict__ vh, const __nv_bfloat16* __restrict__ vl,
    const int* __restrict__ mask,
    __nv_bfloat16* __restrict__ oh, __nv_bfloat16* __restrict__ ol)
{
    __shared__ char ring[3][16384];

    const int tid = threadIdx.x, lane = tid & 31, w = tid >> 5;
    const int q0 = blockIdx.x * 128;
    const int bh_ = blockIdx.y;
    const int b = bh_ >> 4, h = bh_ & 15;
    const int er = lane >> 2, qq = lane & 3;

    uint32_t rb[3];
    rb[0] = smem_u32(ring[0]); rb[1] = smem_u32(ring[1]); rb[2] = smem_u32(ring[2]);

    // ---- stage Q (Qh -> slot0, Ql -> slot1), swizzled -----------------------
    {
        const int row = tid >> 1;
        const int u0 = (tid & 1) * 4;
        const char* sh = (const char*)(qh + (size_t)(b * SEQ + q0 + row) * DIM + h * DK);
        const char* sl = (const char*)(ql + (size_t)(b * SEQ + q0 + row) * DIM + h * DK);
        #pragma unroll
        for (int u = 0; u < 4; u++) {
            const uint32_t off = (uint32_t)(row * 128 + (((u0 + u) ^ (row & 7)) << 4));
            cpasync16(rb[0] + off, sh + (u0 + u) * 16);
            cpasync16(rb[1] + off, sl + (u0 + u) * 16);
        }
        asm volatile("cp.async.commit_group;" ::: "memory");
        asm volatile("cp.async.wait_group 0;" ::: "memory");
        __syncthreads();
    }

    // Q fragments: [h/l][kstep][4]
    uint32_t qf[2][4][4];
    {
        const int row = w * 16 + (lane & 15);
        const int rx = row & 7;
        #pragma unroll
        for (int ks = 0; ks < 4; ks++) {
            const uint32_t addr = (uint32_t)(row * 128 + (((2 * ks + (lane >> 4)) ^ rx) << 4));
            ldmat4(qf[0][ks], rb[0] + addr);
            ldmat4(qf[1][ks], rb[1] + addr);
        }
    }
    __syncthreads();   // ring slots free for K/V now

    // lane-constant address parts
    const int kx = lane & 7;
    const uint32_t kkbase = (uint32_t)(((((lane >> 4) << 3) + (lane & 7))) * 128);
    const uint32_t kvbase = (uint32_t)(((((lane >> 3) & 1) << 3) + (lane & 7)) * 128);
    uint32_t xk[4], xv[4];
    #pragma unroll
    for (int ks = 0; ks < 4; ks++)
        xk[ks] = (uint32_t)((((2 * ks + ((lane >> 3) & 1)) ^ kx)) << 4);
    #pragma unroll
    for (int t = 0; t < 4; t++)
        xv[t] = (uint32_t)((((2 * t + (lane >> 4)) ^ kx)) << 4);

    // resource loader: r even -> K tile r/2, r odd -> V tile r/2; slot r%3
    const int lrow = tid >> 2;
    const int lu0 = (tid & 3) * 2;
    auto load_res = [&](int r) {
        const int kt = r >> 1;
        const __nv_bfloat16* sh = (r & 1) ? vh : kh;
        const __nv_bfloat16* sl = (r & 1) ? vl : kl;
        const char* gh = (const char*)(sh + (size_t)(b * SEQ + kt * 64 + lrow) * DIM + h * DK);
        const char* gl = (const char*)(sl + (size_t)(b * SEQ + kt * 64 + lrow) * DIM + h * DK);
        const uint32_t base = rb[r % 3] + (uint32_t)(lrow * 128);
        #pragma unroll
        for (int u = 0; u < 2; u++) {
            const uint32_t off = (uint32_t)((((lu0 + u) ^ (lrow & 7)) << 4));
            cpasync16(base + off,        gh + (lu0 + u) * 16);
            cpasync16(base + 8192 + off, gl + (lu0 + u) * 16);
        }
        asm volatile("cp.async.commit_group;" ::: "memory");
    };

    float m[2] = {-CUDART_INF_F, -CUDART_INF_F};
    float l[2] = {0.f, 0.f};
    float oacc[8][4];
    #pragma unroll
    for (int n = 0; n < 8; n++)
        #pragma unroll
        for (int i = 0; i < 4; i++) oacc[n][i] = 0.f;

    uint32_t phx[8], phy[8], plx[8], ply[8];
    const int* maskB = mask + b * SEQ;

    load_res(0);
    load_res(1);

    #pragma unroll 1
    for (int kt = 0; kt < ANKT; kt++) {
        // ================= S step (resource 2kt, slot (2kt)%3) ==============
        asm volatile("cp.async.wait_group 1;" ::: "memory");  // res 2kt done
        __syncthreads();                       // all warps done with V(kt-1) slot
        if (kt + 1 < ANKT) load_res(2 * kt + 2);   // writes V(kt-1)'s slot
        {
            const uint32_t sb = rb[(2 * kt) % 3];
            float sacc[8][4];
            #pragma unroll
            for (int n = 0; n < 8; n++)
                #pragma unroll
                for (int i = 0; i < 4; i++) sacc[n][i] = 0.f;

            #pragma unroll
            for (int ks = 0; ks < 4; ks++) {
                uint32_t bf_[4][4];
                #pragma unroll
                for (int p = 0; p < 4; p++)
                    ldmat4(bf_[p], sb + p * 2048 + kkbase + xk[ks]);
                #pragma unroll
                for (int nt = 0; nt < 8; nt++)
                    mma_bf16(sacc[nt], qf[0][ks], &bf_[nt >> 1][(nt & 1) * 2]);
                #pragma unroll
                for (int nt = 0; nt < 8; nt++)
                    mma_bf16(sacc[nt], qf[1][ks], &bf_[nt >> 1][(nt & 1) * 2]);
                #pragma unroll
                for (int p = 0; p < 4; p++)
                    ldmat4(bf_[p], sb + 8192 + p * 2048 + kkbase + xk[ks]);
                #pragma unroll
                for (int nt = 0; nt < 8; nt++)
                    mma_bf16(sacc[nt], qf[0][ks], &bf_[nt >> 1][(nt & 1) * 2]);
            }

            // mask (exactly -1e30, as reference), row max
            float mx0 = -CUDART_INF_F, mx1 = -CUDART_INF_F;
            #pragma unroll
            for (int nt = 0; nt < 8; nt++) {
                int2 mk = *(const int2*)&maskB[kt * 64 + nt * 8 + 2 * qq];
                if (mk.x) { sacc[nt][0] = -1e30f; sacc[nt][2] = -1e30f; }
                if (mk.y) { sacc[nt][1] = -1e30f; sacc[nt][3] = -1e30f; }
                mx0 = fmaxf(mx0, fmaxf(sacc[nt][0], sacc[nt][1]));
                mx1 = fmaxf(mx1, fmaxf(sacc[nt][2], sacc[nt][3]));
            }
            mx0 = fmaxf(mx0, __shfl_xor_sync(0xffffffffu, mx0, 1));
            mx0 = fmaxf(mx0, __shfl_xor_sync(0xffffffffu, mx0, 2));
            mx1 = fmaxf(mx1, __shfl_xor_sync(0xffffffffu, mx1, 1));
            mx1 = fmaxf(mx1, __shfl_xor_sync(0xffffffffu, mx1, 2));

            const float mn0 = fmaxf(m[0], mx0), mn1 = fmaxf(m[1], mx1);
            const float al0 = __expf(m[0] - mn0), al1 = __expf(m[1] - mn1);
            m[0] = mn0; m[1] = mn1;

            float rs0 = 0.f, rs1 = 0.f;
            #pragma unroll
            for (int nt = 0; nt < 8; nt++) {
                const float p0 = __expf(sacc[nt][0] - mn0);
                const float p1 = __expf(sacc[nt][1] - mn0);
                const float p2 = __expf(sacc[nt][2] - mn1);
                const float p3 = __expf(sacc[nt][3] - mn1);
                rs0 += p0 + p1; rs1 += p2 + p3;
                const uint32_t hA = cvt2(p1, p0);
                const uint32_t hB = cvt2(p3, p2);
                phx[nt] = hA; phy[nt] = hB;
                plx[nt] = cvt2(p1 - __uint_as_float(hA & 0xffff0000u),
                               p0 - __uint_as_float(hA << 16));
                ply[nt] = cvt2(p3 - __uint_as_float(hB & 0xffff0000u),
                               p2 - __uint_as_float(hB << 16));
            }
            rs0 += __shfl_xor_sync(0xffffffffu, rs0, 1);
            rs0 += __shfl_xor_sync(0xffffffffu, rs0, 2);
            rs1 += __shfl_xor_sync(0xffffffffu, rs1, 1);
            rs1 += __shfl_xor_sync(0xffffffffu, rs1, 2);
            l[0] = l[0] * al0 + rs0;
            l[1] = l[1] * al1 + rs1;

            #pragma unroll
            for (int n = 0; n < 8; n++) {
                oacc[n][0] *= al0; oacc[n][1] *= al0;
                oacc[n][2] *= al1; oacc[n][3] *= al1;
            }
        }

        // ================= PV step (resource 2kt+1, slot (2kt+1)%3) =========
        if (kt + 1 < ANKT) asm volatile("cp.async.wait_group 1;" ::: "memory");
        else               asm volatile("cp.async.wait_group 0;" ::: "memory");
        __syncthreads();                       // all warps done with K(kt) slot
        if (kt + 1 < ANKT) load_res(2 * kt + 3);   // writes K(kt)'s slot
        {
            const uint32_t sb = rb[(2 * kt + 1) % 3];
            #pragma unroll
            for (int j = 0; j < 4; j++) {
                uint32_t aH[4] = {phx[2 * j], phy[2 * j], phx[2 * j + 1], phy[2 * j + 1]};
                uint32_t aL[4] = {plx[2 * j], ply[2 * j], plx[2 * j + 1], ply[2 * j + 1]};
                uint32_t bv_[4][4];
                #pragma unroll
                for (int t = 0; t < 4; t++)
                    ldmat4t(bv_[t], sb + j * 2048 + kvbase + xv[t]);
                #pragma unroll
                for (int n = 0; n < 8; n++)
                    mma_bf16(oacc[n], aH, &bv_[n >> 1][(n & 1) * 2]);
                #pragma unroll
                for (int n = 0; n < 8; n++)
                    mma_bf16(oacc[n], aL, &bv_[n >> 1][(n & 1) * 2]);
                #pragma unroll
                for (int t = 0; t < 4; t++)
                    ldmat4t(bv_[t], sb + 8192 + j * 2048 + kvbase + xv[t]);
                #pragma unroll
                for (int n = 0; n < 8; n++)
                    mma_bf16(oacc[n], aH, &bv_[n >> 1][(n & 1) * 2]);
            }
        }
    }

    // ---- epilogue: normalize + fused hi/lo split ---------------------------
    const float inv0 = 1.f / l[0], inv1 = 1.f / l[1];
    const int row0 = b * SEQ + q0 + w * 16 + er;
    const size_t base0 = (size_t)row0 * DIM + h * DK + 2 * qq;
    const size_t base1 = base0 + (size_t)8 * DIM;
    #pragma unroll
    for (int n = 0; n < 8; n++) {
        uint32_t hp, lp;
        split2(oacc[n][0] * inv0, oacc[n][1] * inv0, hp, lp);
        *(uint32_t*)&oh[base0 + n * 8] = hp;
        *(uint32_t*)&ol[base0 + n * 8] = lp;
        split2(oacc[n][2] * inv1, oacc[n][3] * inv1, hp, lp);
        *(uint32_t*)&oh[base1 + n * 8] = hp;
        *(uint32_t*)&ol[base1 + n * 8] = lp;
    }
}

// ---------------------------------------------------------------------------
extern "C" void kernel_launch(void* const* d_in, const int* in_sizes, int n_in,
                              void* d_out, int out_size)
{
    const float* x    = (const float*)d_in[0];
    const int*   mask = (const int*)  d_in[1];
    const float* Wq   = (const float*)d_in[2];
    const float* bq   = (const float*)d_in[3];
    const float* Wk   = (const float*)d_in[4];
    const float* bk   = (const float*)d_in[5];
    const float* Wv   = (const float*)d_in[6];
    const float* bv   = (const float*)d_in[7];
    const float* Wf   = (const float*)d_in[8];
    const float* bf   = (const float*)d_in[9];
    float* out = (float*)d_out;

    __nv_bfloat16 *xh, *xl, *ah, *al, *wh, *wl, *qh, *ql, *kh, *kl, *vh, *vl;
    cudaGetSymbolAddress((void**)&xh, g_xh);
    cudaGetSymbolAddress((void**)&xl, g_xl);
    cudaGetSymbolAddress((void**)&ah, g_ah);
    cudaGetSymbolAddress((void**)&al, g_al);
    cudaGetSymbolAddress((void**)&wh, g_wh);
    cudaGetSymbolAddress((void**)&wl, g_wl);
    cudaGetSymbolAddress((void**)&qh, g_qh);
    cudaGetSymbolAddress((void**)&ql, g_ql);
    cudaGetSymbolAddress((void**)&kh, g_kh);
    cudaGetSymbolAddress((void**)&kl, g_kl);
    cudaGetSymbolAddress((void**)&vh, g_vh);
    cudaGetSymbolAddress((void**)&vl, g_vl);

    const int n4 = MTOT * DIM / 4;
    dim3 tblk(32, 8), tgrd(32, 32);
    dim3 ggrd(8, 64), gblk(256);

    split_f32<<<n4 / 256, 256>>>((const float4*)x, (uint2*)xh, (uint2*)xl, 1.f);
    wsplit_t<<<tgrd, tblk>>>(Wq, wh + 0 * DIM * DIM, wl + 0 * DIM * DIM);
    wsplit_t<<<tgrd, tblk>>>(Wk, wh + 1 * DIM * DIM, wl + 1 * DIM * DIM);
    wsplit_t<<<tgrd, tblk>>>(Wv, wh + 2 * DIM * DIM, wl + 2 * DIM * DIM);
    wsplit_t<<<tgrd, tblk>>>(Wf, wh + 3 * DIM * DIM, wl + 3 * DIM * DIM);

    // Q/K/V projections with fused hi/lo split epilogues
    gemm_mma_split<<<ggrd, gblk>>>(xh, xl, wh + 0 * DIM * DIM, wl + 0 * DIM * DIM,
                                   bq, nullptr, qh, ql, ATTN_SCALE);
    gemm_mma_split<<<ggrd, gblk>>>(xh, xl, wh + 1 * DIM * DIM, wl + 1 * DIM * DIM,
                                   bk, nullptr, kh, kl, 1.f);
    gemm_mma_split<<<ggrd, gblk>>>(xh, xl, wh + 2 * DIM * DIM, wl + 2 * DIM * DIM,
                                   bv, nullptr, vh, vl, 1.f);

    dim3 attn_grid(SEQ / 128, BSZ * NH), attn_blk(256);
    attn_mma<<<attn_grid, attn_blk>>>(qh, ql, kh, kl, vh, vl, mask, ah, al);

    // Final projection, fp32 output
    gemm_mma_split<<<ggrd, gblk>>>(ah, al, wh + 3 * DIM * DIM, wl + 3 * DIM * DIM,
                                   bf, out, nullptr, nullptr, 1.f);
}

// round 17
// speedup vs baseline: 3.2958x; 1.0468x over previous
#include <cuda_runtime.h>
#include <cuda_bf16.h>
#include <math_constants.h>
#include <cstdint>

#define BSZ 4
#define SEQ 2048
#define DIM 1024
#define NH  16
#define DK  64
#define ATTN_SCALE 0.125f
#define MTOT (BSZ*SEQ)   // 8192

// ---------------- scratch (device globals: allocation-guard safe) ----------
__device__ __nv_bfloat16 g_xh[MTOT*DIM];
__device__ __nv_bfloat16 g_xl[MTOT*DIM];
__device__ __nv_bfloat16 g_ah[MTOT*DIM];
__device__ __nv_bfloat16 g_al[MTOT*DIM];
__device__ __nv_bfloat16 g_qh[MTOT*DIM];
__device__ __nv_bfloat16 g_ql[MTOT*DIM];
__device__ __nv_bfloat16 g_kh[MTOT*DIM];
__device__ __nv_bfloat16 g_kl[MTOT*DIM];
__device__ __nv_bfloat16 g_vh[MTOT*DIM];
__device__ __nv_bfloat16 g_vl[MTOT*DIM];
__device__ __nv_bfloat16 g_wh[4][DIM*DIM];   // W^T hi  [n][k]
__device__ __nv_bfloat16 g_wl[4][DIM*DIM];   // W^T lo  [n][k]

// ---------------- PTX helpers ----------------------------------------------
__device__ __forceinline__ uint32_t smem_u32(const void* p) {
    uint32_t a;
    asm("{ .reg .u64 t; cvta.to.shared.u64 t, %1; cvt.u32.u64 %0, t; }"
        : "=r"(a) : "l"(p));
    return a;
}

__device__ __forceinline__ void cpasync16(uint32_t dst, const void* src) {
    asm volatile("cp.async.cg.shared.global [%0], [%1], 16;"
        :: "r"(dst), "l"(src) : "memory");
}

__device__ __forceinline__ void ldmat4(uint32_t* r, uint32_t addr) {
    asm volatile("ldmatrix.sync.aligned.m8n8.x4.shared.b16 {%0,%1,%2,%3}, [%4];"
        : "=r"(r[0]), "=r"(r[1]), "=r"(r[2]), "=r"(r[3]) : "r"(addr));
}

__device__ __forceinline__ void ldmat4t(uint32_t* r, uint32_t addr) {
    asm volatile("ldmatrix.sync.aligned.m8n8.x4.trans.shared.b16 {%0,%1,%2,%3}, [%4];"
        : "=r"(r[0]), "=r"(r[1]), "=r"(r[2]), "=r"(r[3]) : "r"(addr));
}

// D (fp32) += A (bf16) * B (bf16), m16n8k16
__device__ __forceinline__ void mma_bf16(float* d, const uint32_t* a, const uint32_t* b) {
    asm volatile("mma.sync.aligned.m16n8k16.row.col.f32.bf16.bf16.f32 "
        "{%0,%1,%2,%3}, {%4,%5,%6,%7}, {%8,%9}, {%0,%1,%2,%3};"
        : "+f"(d[0]), "+f"(d[1]), "+f"(d[2]), "+f"(d[3])
        : "r"(a[0]), "r"(a[1]), "r"(a[2]), "r"(a[3]), "r"(b[0]), "r"(b[1]));
}

// pack two f32 -> bf16x2 register {hi, lo}
__device__ __forceinline__ uint32_t cvt2(float hi, float lo) {
    uint32_t r;
    asm("cvt.rn.bf16x2.f32 %0, %1, %2;" : "=r"(r) : "f"(hi), "f"(lo));
    return r;
}

// split two fp32 into bf16-hi pair and bf16-lo pair (packed bf16x2 each)
__device__ __forceinline__ void split2(float v0, float v1, uint32_t& hp, uint32_t& lp) {
    hp = cvt2(v1, v0);   // {lo-half = v0, hi-half = v1}
    lp = cvt2(v1 - __uint_as_float(hp & 0xffff0000u),
              v0 - __uint_as_float(hp << 16));
}

// ---------------------------------------------------------------------------
// Split fp32 -> bf16 hi + bf16 lo (used only for the input x)
// ---------------------------------------------------------------------------
__device__ __forceinline__ uint32_t bfpack(__nv_bfloat16 a, __nv_bfloat16 b) {
    __nv_bfloat162 t = __halves2bfloat162(a, b);
    return *reinterpret_cast<uint32_t*>(&t);
}

__global__ __launch_bounds__(256) void split_f32(
    const float4* __restrict__ in, uint2* __restrict__ hi, uint2* __restrict__ lo,
    float scale)
{
    const int i = blockIdx.x * 256 + threadIdx.x;
    float4 v = in[i];
    v.x *= scale; v.y *= scale; v.z *= scale; v.w *= scale;
    __nv_bfloat16 hx = __float2bfloat16(v.x);
    __nv_bfloat16 hy = __float2bfloat16(v.y);
    __nv_bfloat16 hz = __float2bfloat16(v.z);
    __nv_bfloat16 hw = __float2bfloat16(v.w);
    __nv_bfloat16 lx = __float2bfloat16(v.x - __bfloat162float(hx));
    __nv_bfloat16 ly = __float2bfloat16(v.y - __bfloat162float(hy));
    __nv_bfloat16 lz = __float2bfloat16(v.z - __bfloat162float(hz));
    __nv_bfloat16 lw = __float2bfloat16(v.w - __bfloat162float(hw));
    hi[i] = make_uint2(bfpack(hx, hy), bfpack(hz, hw));
    lo[i] = make_uint2(bfpack(lx, ly), bfpack(lz, lw));
}

// ---------------------------------------------------------------------------
// Transpose + split W[k][n] -> Wt_hi/lo [n][k]
// ---------------------------------------------------------------------------
__global__ __launch_bounds__(256) void wsplit_t(
    const float* __restrict__ W, __nv_bfloat16* __restrict__ th,
    __nv_bfloat16* __restrict__ tl)
{
    __shared__ float s[32][33];
    const int tx = threadIdx.x, ty = threadIdx.y;
    const int bx = blockIdx.x, by = blockIdx.y;
    #pragma unroll
    for (int j = 0; j < 32; j += 8)
        s[ty + j][tx] = W[(by * 32 + ty + j) * DIM + bx * 32 + tx];
    __syncthreads();
    #pragma unroll
    for (int j = 0; j < 32; j += 8) {
        float v = s[tx][ty + j];
        __nv_bfloat16 h = __float2bfloat16(v);
        int o = (bx * 32 + ty + j) * DIM + by * 32 + tx;
        th[o] = h;
        tl[o] = __float2bfloat16(v - __bfloat162float(h));
    }
}

// ---------------------------------------------------------------------------
// Shared GEMM mainloop pieces (R14/R15 proven layout):
// 3-stage pipeline, 48KB static smem, tiles 128 rows x 32B, 16B-unit XOR
// swizzle phys = row*32 + ((u ^ ((row>>2)&1)) << 4).
// ---------------------------------------------------------------------------
#define GBK    16
#define GNCH   (DIM / GBK)         // 64 chunks
#define GTILE  4096                // 128 rows * 32 B
#define GSTAGE (4 * GTILE)         // Ah | Al | Bh | Bl

struct QKVPtrs {
    const float* bias0; const float* bias1; const float* bias2;
    __nv_bfloat16 *h0, *l0, *h1, *l1, *h2, *l2;
};

// Macro-free inline mainloop via a device function operating on accumulator.
// (Kept as code duplication in the two kernels for simplicity/regs.)

// ---------------- fused Q/K/V GEMM: grid.z selects W/bias/output ------------
__global__ __launch_bounds__(256, 2) void gemm_qkv(
    const __nv_bfloat16* __restrict__ Ah, const __nv_bfloat16* __restrict__ Al,
    const __nv_bfloat16* __restrict__ WhBase, const __nv_bfloat16* __restrict__ WlBase,
    QKVPtrs p)
{
    __shared__ char smem[3][4][GTILE];

    const int tid  = threadIdx.x;
    const int lane = tid & 31, wid = tid >> 5;
    const int m0 = blockIdx.y * 128, n0 = blockIdx.x * 128;
    const int z  = blockIdx.z;
    const int wm = (wid & 3) * 32;
    const int wn = (wid >> 2) * 64;

    const __nv_bfloat16* Bh = WhBase + (size_t)z * DIM * DIM;
    const __nv_bfloat16* Bl = WlBase + (size_t)z * DIM * DIM;
    const float* bias = (z == 0) ? p.bias0 : (z == 1) ? p.bias1 : p.bias2;
    __nv_bfloat16* Chi = (z == 0) ? p.h0 : (z == 1) ? p.h1 : p.h2;
    __nv_bfloat16* Clo = (z == 0) ? p.l0 : (z == 1) ? p.l1 : p.l2;
    const float scale = (z == 0) ? ATTN_SCALE : 1.f;

    const int trow = tid >> 1, thalf = tid & 1;
    const char* gsrc0 = (const char*)(Ah + (size_t)(m0 + trow) * DIM) + thalf * 16;
    const char* gsrc1 = (const char*)(Al + (size_t)(m0 + trow) * DIM) + thalf * 16;
    const char* gsrc2 = (const char*)(Bh + (size_t)(n0 + trow) * DIM) + thalf * 16;
    const char* gsrc3 = (const char*)(Bl + (size_t)(n0 + trow) * DIM) + thalf * 16;
    const uint32_t doff =
        (uint32_t)(trow * 32 + ((thalf ^ ((trow >> 2) & 1)) << 4));
    const uint32_t sb = smem_u32(&smem[0][0][0]);

    uint32_t aoff[2];
    #pragma unroll
    for (int mt = 0; mt < 2; mt++) {
        const int row = wm + mt * 16 + (lane & 15);
        aoff[mt] = (uint32_t)(row * 32 + (((lane >> 4) ^ ((row >> 2) & 1)) << 4));
    }
    uint32_t boff[4];
    #pragma unroll
    for (int pq = 0; pq < 4; pq++) {
        const int row = wn + pq * 16 + ((lane >> 4) << 3) + (lane & 7);
        boff[pq] = (uint32_t)(row * 32 + ((((lane >> 3) & 1) ^ ((row >> 2) & 1)) << 4));
    }

    float acc[2][8][4];
    #pragma unroll
    for (int mt = 0; mt < 2; mt++)
        #pragma unroll
        for (int nt = 0; nt < 8; nt++)
            #pragma unroll
            for (int i = 0; i < 4; i++) acc[mt][nt][i] = 0.f;

    auto load_chunk = [&](int c) {
        const uint32_t base = sb + (uint32_t)(c % 3) * GSTAGE + doff;
        const int kb = c * 32;
        cpasync16(base + 0 * GTILE, gsrc0 + kb);
        cpasync16(base + 1 * GTILE, gsrc1 + kb);
        cpasync16(base + 2 * GTILE, gsrc2 + kb);
        cpasync16(base + 3 * GTILE, gsrc3 + kb);
        asm volatile("cp.async.commit_group;" ::: "memory");
    };

    load_chunk(0);
    load_chunk(1);

    #pragma unroll 1
    for (int c = 0; c < GNCH; c++) {
        if (c < GNCH - 1) asm volatile("cp.async.wait_group 1;" ::: "memory");
        else              asm volatile("cp.async.wait_group 0;" ::: "memory");
        __syncthreads();
        if (c + 2 < GNCH) load_chunk(c + 2);

        const uint32_t tb = sb + (uint32_t)(c % 3) * GSTAGE;
        uint32_t af[2][2][4];
        uint32_t bf[2][8][2];
        #pragma unroll
        for (int h = 0; h < 2; h++) {
            const uint32_t ta = tb + h * GTILE;
            #pragma unroll
            for (int mt = 0; mt < 2; mt++) ldmat4(af[h][mt], ta + aoff[mt]);
            const uint32_t tB = tb + (2 + h) * GTILE;
            #pragma unroll
            for (int pq = 0; pq < 4; pq++) {
                uint32_t r[4];
                ldmat4(r, tB + boff[pq]);
                bf[h][pq * 2 + 0][0] = r[0]; bf[h][pq * 2 + 0][1] = r[1];
                bf[h][pq * 2 + 1][0] = r[2]; bf[h][pq * 2 + 1][1] = r[3];
            }
        }

        #pragma unroll
        for (int mt = 0; mt < 2; mt++)
            #pragma unroll
            for (int nt = 0; nt < 8; nt++)
                mma_bf16(acc[mt][nt], af[0][mt], bf[0][nt]);
        #pragma unroll
        for (int mt = 0; mt < 2; mt++)
            #pragma unroll
            for (int nt = 0; nt < 8; nt++)
                mma_bf16(acc[mt][nt], af[0][mt], bf[1][nt]);
        #pragma unroll
        for (int mt = 0; mt < 2; mt++)
            #pragma unroll
            for (int nt = 0; nt < 8; nt++)
                mma_bf16(acc[mt][nt], af[1][mt], bf[0][nt]);
    }

    const int er = lane >> 2, ec = (lane & 3) * 2;
    #pragma unroll
    for (int mt = 0; mt < 2; mt++) {
        const int row = m0 + wm + mt * 16 + er;
        #pragma unroll
        for (int nt = 0; nt < 8; nt++) {
            const int col = n0 + wn + nt * 8 + ec;
            const float b0 = bias[col], b1 = bias[col + 1];
            uint32_t hp, lp;
            split2((acc[mt][nt][0] + b0) * scale, (acc[mt][nt][1] + b1) * scale, hp, lp);
            *(uint32_t*)&Chi[(size_t)row * DIM + col] = hp;
            *(uint32_t*)&Clo[(size_t)row * DIM + col] = lp;
            split2((acc[mt][nt][2] + b0) * scale, (acc[mt][nt][3] + b1) * scale, hp, lp);
            *(uint32_t*)&Chi[(size_t)(row + 8) * DIM + col] = hp;
            *(uint32_t*)&Clo[(size_t)(row + 8) * DIM + col] = lp;
        }
    }
}

// ---------------- final projection GEMM: fp32 output ------------------------
__global__ __launch_bounds__(256, 2) void gemm_out(
    const __nv_bfloat16* __restrict__ Ah, const __nv_bfloat16* __restrict__ Al,
    const __nv_bfloat16* __restrict__ Bh, const __nv_bfloat16* __restrict__ Bl,
    const float* __restrict__ bias, float* __restrict__ C)
{
    __shared__ char smem[3][4][GTILE];

    const int tid  = threadIdx.x;
    const int lane = tid & 31, wid = tid >> 5;
    const int m0 = blockIdx.y * 128, n0 = blockIdx.x * 128;
    const int wm = (wid & 3) * 32;
    const int wn = (wid >> 2) * 64;

    const int trow = tid >> 1, thalf = tid & 1;
    const char* gsrc0 = (const char*)(Ah + (size_t)(m0 + trow) * DIM) + thalf * 16;
    const char* gsrc1 = (const char*)(Al + (size_t)(m0 + trow) * DIM) + thalf * 16;
    const char* gsrc2 = (const char*)(Bh + (size_t)(n0 + trow) * DIM) + thalf * 16;
    const char* gsrc3 = (const char*)(Bl + (size_t)(n0 + trow) * DIM) + thalf * 16;
    const uint32_t doff =
        (uint32_t)(trow * 32 + ((thalf ^ ((trow >> 2) & 1)) << 4));
    const uint32_t sb = smem_u32(&smem[0][0][0]);

    uint32_t aoff[2];
    #pragma unroll
    for (int mt = 0; mt < 2; mt++) {
        const int row = wm + mt * 16 + (lane & 15);
        aoff[mt] = (uint32_t)(row * 32 + (((lane >> 4) ^ ((row >> 2) & 1)) << 4));
    }
    uint32_t boff[4];
    #pragma unroll
    for (int pq = 0; pq < 4; pq++) {
        const int row = wn + pq * 16 + ((lane >> 4) << 3) + (lane & 7);
        boff[pq] = (uint32_t)(row * 32 + ((((lane >> 3) & 1) ^ ((row >> 2) & 1)) << 4));
    }

    float acc[2][8][4];
    #pragma unroll
    for (int mt = 0; mt < 2; mt++)
        #pragma unroll
        for (int nt = 0; nt < 8; nt++)
            #pragma unroll
            for (int i = 0; i < 4; i++) acc[mt][nt][i] = 0.f;

    auto load_chunk = [&](int c) {
        const uint32_t base = sb + (uint32_t)(c % 3) * GSTAGE + doff;
        const int kb = c * 32;
        cpasync16(base + 0 * GTILE, gsrc0 + kb);
        cpasync16(base + 1 * GTILE, gsrc1 + kb);
        cpasync16(base + 2 * GTILE, gsrc2 + kb);
        cpasync16(base + 3 * GTILE, gsrc3 + kb);
        asm volatile("cp.async.commit_group;" ::: "memory");
    };

    load_chunk(0);
    load_chunk(1);

    #pragma unroll 1
    for (int c = 0; c < GNCH; c++) {
        if (c < GNCH - 1) asm volatile("cp.async.wait_group 1;" ::: "memory");
        else              asm volatile("cp.async.wait_group 0;" ::: "memory");
        __syncthreads();
        if (c + 2 < GNCH) load_chunk(c + 2);

        const uint32_t tb = sb + (uint32_t)(c % 3) * GSTAGE;
        uint32_t af[2][2][4];
        uint32_t bf[2][8][2];
        #pragma unroll
        for (int h = 0; h < 2; h++) {
            const uint32_t ta = tb + h * GTILE;
            #pragma unroll
            for (int mt = 0; mt < 2; mt++) ldmat4(af[h][mt], ta + aoff[mt]);
            const uint32_t tB = tb + (2 + h) * GTILE;
            #pragma unroll
            for (int pq = 0; pq < 4; pq++) {
                uint32_t r[4];
                ldmat4(r, tB + boff[pq]);
                bf[h][pq * 2 + 0][0] = r[0]; bf[h][pq * 2 + 0][1] = r[1];
                bf[h][pq * 2 + 1][0] = r[2]; bf[h][pq * 2 + 1][1] = r[3];
            }
        }

        #pragma unroll
        for (int mt = 0; mt < 2; mt++)
            #pragma unroll
            for (int nt = 0; nt < 8; nt++)
                mma_bf16(acc[mt][nt], af[0][mt], bf[0][nt]);
        #pragma unroll
        for (int mt = 0; mt < 2; mt++)
            #pragma unroll
            for (int nt = 0; nt < 8; nt++)
                mma_bf16(acc[mt][nt], af[0][mt], bf[1][nt]);
        #pragma unroll
        for (int mt = 0; mt < 2; mt++)
            #pragma unroll
            for (int nt = 0; nt < 8; nt++)
                mma_bf16(acc[mt][nt], af[1][mt], bf[0][nt]);
    }

    const int er = lane >> 2, ec = (lane & 3) * 2;
    #pragma unroll
    for (int mt = 0; mt < 2; mt++) {
        const int row = m0 + wm + mt * 16 + er;
        #pragma unroll
        for (int nt = 0; nt < 8; nt++) {
            const int col = n0 + wn + nt * 8 + ec;
            const float b0 = bias[col], b1 = bias[col + 1];
            *(float2*)&C[(size_t)row * DIM + col] =
                make_float2(acc[mt][nt][0] + b0, acc[mt][nt][1] + b1);
            *(float2*)&C[(size_t)(row + 8) * DIM + col] =
                make_float2(acc[mt][nt][2] + b0, acc[mt][nt][3] + b1);
        }
    }
}

// ---------------------------------------------------------------------------
// Flash attention via mma.sync bf16 hi/lo split (R14/R15 kernel, unchanged).
// ---------------------------------------------------------------------------
#define ANKT (SEQ / 64)            // 32 key tiles

__global__ __launch_bounds__(256) void attn_mma(
    const __nv_bfloat16* __restrict__ qh, const __nv_bfloat16* __restrict__ ql,
    const __nv_bfloat16* __restrict__ kh, const __nv_bfloat16* __restrict__ kl,
    const __nv_bfloat16* __restrict__ vh, const __nv_bfloat16* __restrict__ vl,
    const int* __restrict__ mask,
    __nv_bfloat16* __restrict__ oh, __nv_bfloat16* __restrict__ ol)
{
    __shared__ char ring[3][16384];

    const int tid = threadIdx.x, lane = tid & 31, w = tid >> 5;
    const int q0 = blockIdx.x * 128;
    const int bh_ = blockIdx.y;
    const int b = bh_ >> 4, h = bh_ & 15;
    const int er = lane >> 2, qq = lane & 3;

    uint32_t rb[3];
    rb[0] = smem_u32(ring[0]); rb[1] = smem_u32(ring[1]); rb[2] = smem_u32(ring[2]);

    // ---- stage Q (Qh -> slot0, Ql -> slot1), swizzled -----------------------
    {
        const int row = tid >> 1;
        const int u0 = (tid & 1) * 4;
        const char* sh = (const char*)(qh + (size_t)(b * SEQ + q0 + row) * DIM + h * DK);
        const char* sl = (const char*)(ql + (size_t)(b * SEQ + q0 + row) * DIM + h * DK);
        #pragma unroll
        for (int u = 0; u < 4; u++) {
            const uint32_t off = (uint32_t)(row * 128 + (((u0 + u) ^ (row & 7)) << 4));
            cpasync16(rb[0] + off, sh + (u0 + u) * 16);
            cpasync16(rb[1] + off, sl + (u0 + u) * 16);
        }
        asm volatile("cp.async.commit_group;" ::: "memory");
        asm volatile("cp.async.wait_group 0;" ::: "memory");
        __syncthreads();
    }

    // Q fragments: [h/l][kstep][4]
    uint32_t qf[2][4][4];
    {
        const int row = w * 16 + (lane & 15);
        const int rx = row & 7;
        #pragma unroll
        for (int ks = 0; ks < 4; ks++) {
            const uint32_t addr = (uint32_t)(row * 128 + (((2 * ks + (lane >> 4)) ^ rx) << 4));
            ldmat4(qf[0][ks], rb[0] + addr);
            ldmat4(qf[1][ks], rb[1] + addr);
        }
    }
    __syncthreads();   // ring slots free for K/V now

    // lane-constant address parts
    const int kx = lane & 7;
    const uint32_t kkbase = (uint32_t)(((((lane >> 4) << 3) + (lane & 7))) * 128);
    const uint32_t kvbase = (uint32_t)(((((lane >> 3) & 1) << 3) + (lane & 7)) * 128);
    uint32_t xk[4], xv[4];
    #pragma unroll
    for (int ks = 0; ks < 4; ks++)
        xk[ks] = (uint32_t)((((2 * ks + ((lane >> 3) & 1)) ^ kx)) << 4);
    #pragma unroll
    for (int t = 0; t < 4; t++)
        xv[t] = (uint32_t)((((2 * t + (lane >> 4)) ^ kx)) << 4);

    // resource loader: r even -> K tile r/2, r odd -> V tile r/2; slot r%3
    const int lrow = tid >> 2;
    const int lu0 = (tid & 3) * 2;
    auto load_res = [&](int r) {
        const int kt = r >> 1;
        const __nv_bfloat16* sh = (r & 1) ? vh : kh;
        const __nv_bfloat16* sl = (r & 1) ? vl : kl;
        const char* gh = (const char*)(sh + (size_t)(b * SEQ + kt * 64 + lrow) * DIM + h * DK);
        const char* gl = (const char*)(sl + (size_t)(b * SEQ + kt * 64 + lrow) * DIM + h * DK);
        const uint32_t base = rb[r % 3] + (uint32_t)(lrow * 128);
        #pragma unroll
        for (int u = 0; u < 2; u++) {
            const uint32_t off = (uint32_t)((((lu0 + u) ^ (lrow & 7)) << 4));
            cpasync16(base + off,        gh + (lu0 + u) * 16);
            cpasync16(base + 8192 + off, gl + (lu0 + u) * 16);
        }
        asm volatile("cp.async.commit_group;" ::: "memory");
    };

    float m[2] = {-CUDART_INF_F, -CUDART_INF_F};
    float l[2] = {0.f, 0.f};
    float oacc[8][4];
    #pragma unroll
    for (int n = 0; n < 8; n++)
        #pragma unroll
        for (int i = 0; i < 4; i++) oacc[n][i] = 0.f;

    uint32_t phx[8], phy[8], plx[8], ply[8];
    const int* maskB = mask + b * SEQ;

    load_res(0);
    load_res(1);

    #pragma unroll 1
    for (int kt = 0; kt < ANKT; kt++) {
        // ================= S step (resource 2kt, slot (2kt)%3) ==============
        asm volatile("cp.async.wait_group 1;" ::: "memory");  // res 2kt done
        __syncthreads();                       // all warps done with V(kt-1) slot
        if (kt + 1 < ANKT) load_res(2 * kt + 2);   // writes V(kt-1)'s slot
        {
            const uint32_t sb = rb[(2 * kt) % 3];
            float sacc[8][4];
            #pragma unroll
            for (int n = 0; n < 8; n++)
                #pragma unroll
                for (int i = 0; i < 4; i++) sacc[n][i] = 0.f;

            #pragma unroll
            for (int ks = 0; ks < 4; ks++) {
                uint32_t bf_[4][4];
                #pragma unroll
                for (int p = 0; p < 4; p++)
                    ldmat4(bf_[p], sb + p * 2048 + kkbase + xk[ks]);
                #pragma unroll
                for (int nt = 0; nt < 8; nt++)
                    mma_bf16(sacc[nt], qf[0][ks], &bf_[nt >> 1][(nt & 1) * 2]);
                #pragma unroll
                for (int nt = 0; nt < 8; nt++)
                    mma_bf16(sacc[nt], qf[1][ks], &bf_[nt >> 1][(nt & 1) * 2]);
                #pragma unroll
                for (int p = 0; p < 4; p++)
                    ldmat4(bf_[p], sb + 8192 + p * 2048 + kkbase + xk[ks]);
                #pragma unroll
                for (int nt = 0; nt < 8; nt++)
                    mma_bf16(sacc[nt], qf[0][ks], &bf_[nt >> 1][(nt & 1) * 2]);
            }

            // mask (exactly -1e30, as reference), row max
            float mx0 = -CUDART_INF_F, mx1 = -CUDART_INF_F;
            #pragma unroll
            for (int nt = 0; nt < 8; nt++) {
                int2 mk = *(const int2*)&maskB[kt * 64 + nt * 8 + 2 * qq];
                if (mk.x) { sacc[nt][0] = -1e30f; sacc[nt][2] = -1e30f; }
                if (mk.y) { sacc[nt][1] = -1e30f; sacc[nt][3] = -1e30f; }
                mx0 = fmaxf(mx0, fmaxf(sacc[nt][0], sacc[nt][1]));
                mx1 = fmaxf(mx1, fmaxf(sacc[nt][2], sacc[nt][3]));
            }
            mx0 = fmaxf(mx0, __shfl_xor_sync(0xffffffffu, mx0, 1));
            mx0 = fmaxf(mx0, __shfl_xor_sync(0xffffffffu, mx0, 2));
            mx1 = fmaxf(mx1, __shfl_xor_sync(0xffffffffu, mx1, 1));
            mx1 = fmaxf(mx1, __shfl_xor_sync(0xffffffffu, mx1, 2));

            const float mn0 = fmaxf(m[0], mx0), mn1 = fmaxf(m[1], mx1);
            const float al0 = __expf(m[0] - mn0), al1 = __expf(m[1] - mn1);
            m[0] = mn0; m[1] = mn1;

            float rs0 = 0.f, rs1 = 0.f;
            #pragma unroll
            for (int nt = 0; nt < 8; nt++) {
                const float p0 = __expf(sacc[nt][0] - mn0);
                const float p1 = __expf(sacc[nt][1] - mn0);
                const float p2 = __expf(sacc[nt][2] - mn1);
                const float p3 = __expf(sacc[nt][3] - mn1);
                rs0 += p0 + p1; rs1 += p2 + p3;
                const uint32_t hA = cvt2(p1, p0);
                const uint32_t hB = cvt2(p3, p2);
                phx[nt] = hA; phy[nt] = hB;
                plx[nt] = cvt2(p1 - __uint_as_float(hA & 0xffff0000u),
                               p0 - __uint_as_float(hA << 16));
                ply[nt] = cvt2(p3 - __uint_as_float(hB & 0xffff0000u),
                               p2 - __uint_as_float(hB << 16));
            }
            rs0 += __shfl_xor_sync(0xffffffffu, rs0, 1);
            rs0 += __shfl_xor_sync(0xffffffffu, rs0, 2);
            rs1 += __shfl_xor_sync(0xffffffffu, rs1, 1);
            rs1 += __shfl_xor_sync(0xffffffffu, rs1, 2);
            l[0] = l[0] * al0 + rs0;
            l[1] = l[1] * al1 + rs1;

            #pragma unroll
            for (int n = 0; n < 8; n++) {
                oacc[n][0] *= al0; oacc[n][1] *= al0;
                oacc[n][2] *= al1; oacc[n][3] *= al1;
            }
        }

        // ================= PV step (resource 2kt+1, slot (2kt+1)%3) =========
        if (kt + 1 < ANKT) asm volatile("cp.async.wait_group 1;" ::: "memory");
        else               asm volatile("cp.async.wait_group 0;" ::: "memory");
        __syncthreads();                       // all warps done with K(kt) slot
        if (kt + 1 < ANKT) load_res(2 * kt + 3);   // writes K(kt)'s slot
        {
            const uint32_t sb = rb[(2 * kt + 1) % 3];
            #pragma unroll
            for (int j = 0; j < 4; j++) {
                uint32_t aH[4] = {phx[2 * j], phy[2 * j], phx[2 * j + 1], phy[2 * j + 1]};
                uint32_t aL[4] = {plx[2 * j], ply[2 * j], plx[2 * j + 1], ply[2 * j + 1]};
                uint32_t bv_[4][4];
                #pragma unroll
                for (int t = 0; t < 4; t++)
                    ldmat4t(bv_[t], sb + j * 2048 + kvbase + xv[t]);
                #pragma unroll
                for (int n = 0; n < 8; n++)
                    mma_bf16(oacc[n], aH, &bv_[n >> 1][(n & 1) * 2]);
                #pragma unroll
                for (int n = 0; n < 8; n++)
                    mma_bf16(oacc[n], aL, &bv_[n >> 1][(n & 1) * 2]);
                #pragma unroll
                for (int t = 0; t < 4; t++)
                    ldmat4t(bv_[t], sb + 8192 + j * 2048 + kvbase + xv[t]);
                #pragma unroll
                for (int n = 0; n < 8; n++)
                    mma_bf16(oacc[n], aH, &bv_[n >> 1][(n & 1) * 2]);
            }
        }
    }

    // ---- epilogue: normalize + fused hi/lo split ---------------------------
    const float inv0 = 1.f / l[0], inv1 = 1.f / l[1];
    const int row0 = b * SEQ + q0 + w * 16 + er;
    const size_t base0 = (size_t)row0 * DIM + h * DK + 2 * qq;
    const size_t base1 = base0 + (size_t)8 * DIM;
    #pragma unroll
    for (int n = 0; n < 8; n++) {
        uint32_t hp, lp;
        split2(oacc[n][0] * inv0, oacc[n][1] * inv0, hp, lp);
        *(uint32_t*)&oh[base0 + n * 8] = hp;
        *(uint32_t*)&ol[base0 + n * 8] = lp;
        split2(oacc[n][2] * inv1, oacc[n][3] * inv1, hp, lp);
        *(uint32_t*)&oh[base1 + n * 8] = hp;
        *(uint32_t*)&ol[base1 + n * 8] = lp;
    }
}

// ---------------------------------------------------------------------------
extern "C" void kernel_launch(void* const* d_in, const int* in_sizes, int n_in,
                              void* d_out, int out_size)
{
    const float* x    = (const float*)d_in[0];
    const int*   mask = (const int*)  d_in[1];
    const float* Wq   = (const float*)d_in[2];
    const float* bq   = (const float*)d_in[3];
    const float* Wk   = (const float*)d_in[4];
    const float* bk   = (const float*)d_in[5];
    const float* Wv   = (const float*)d_in[6];
    const float* bv   = (const float*)d_in[7];
    const float* Wf   = (const float*)d_in[8];
    const float* bf   = (const float*)d_in[9];
    float* out = (float*)d_out;

    __nv_bfloat16 *xh, *xl, *ah, *al, *wh, *wl, *qh, *ql, *kh, *kl, *vh, *vl;
    cudaGetSymbolAddress((void**)&xh, g_xh);
    cudaGetSymbolAddress((void**)&xl, g_xl);
    cudaGetSymbolAddress((void**)&ah, g_ah);
    cudaGetSymbolAddress((void**)&al, g_al);
    cudaGetSymbolAddress((void**)&wh, g_wh);
    cudaGetSymbolAddress((void**)&wl, g_wl);
    cudaGetSymbolAddress((void**)&qh, g_qh);
    cudaGetSymbolAddress((void**)&ql, g_ql);
    cudaGetSymbolAddress((void**)&kh, g_kh);
    cudaGetSymbolAddress((void**)&kl, g_kl);
    cudaGetSymbolAddress((void**)&vh, g_vh);
    cudaGetSymbolAddress((void**)&vl, g_vl);

    const int n4 = MTOT * DIM / 4;
    dim3 tblk(32, 8), tgrd(32, 32);

    split_f32<<<n4 / 256, 256>>>((const float4*)x, (uint2*)xh, (uint2*)xl, 1.f);
    wsplit_t<<<tgrd, tblk>>>(Wq, wh + 0 * DIM * DIM, wl + 0 * DIM * DIM);
    wsplit_t<<<tgrd, tblk>>>(Wk, wh + 1 * DIM * DIM, wl + 1 * DIM * DIM);
    wsplit_t<<<tgrd, tblk>>>(Wv, wh + 2 * DIM * DIM, wl + 2 * DIM * DIM);
    wsplit_t<<<tgrd, tblk>>>(Wf, wh + 3 * DIM * DIM, wl + 3 * DIM * DIM);

    // Fused Q/K/V projection: grid.z picks {Q,K,V}
    QKVPtrs p;
    p.bias0 = bq; p.bias1 = bk; p.bias2 = bv;
    p.h0 = qh; p.l0 = ql; p.h1 = kh; p.l1 = kl; p.h2 = vh; p.l2 = vl;
    dim3 qkv_grid(8, 64, 3), gblk(256);
    gemm_qkv<<<qkv_grid, gblk>>>(xh, xl, wh, wl, p);

    dim3 attn_grid(SEQ / 128, BSZ * NH), attn_blk(256);
    attn_mma<<<attn_grid, attn_blk>>>(qh, ql, kh, kl, vh, vl, mask, ah, al);

    // Final projection, fp32 output
    dim3 out_grid(8, 64);
    gemm_out<<<out_grid, gblk>>>(ah, al, wh + 3 * DIM * DIM, wl + 3 * DIM * DIM,
                                 bf, out);
}